// round 7
// baseline (speedup 1.0000x reference)
#include <cuda_runtime.h>
#include <math.h>
#include <stdint.h>

#define BB 2
#define LQn 2048
#define LKn 2048
#define EE 1024
#define HH 16
#define DD 64

// ---------------- scratch ----------------
__device__ float g_Q[(size_t)BB * LQn * EE];
__device__ float g_K[(size_t)BB * LKn * EE];
__device__ float g_V[(size_t)BB * LKn * EE];
__device__ float g_ctx[(size_t)BB * LQn * EE];
__device__ float g_Sraw[(size_t)BB * HH * LQn * LKn];

// ---------------- helpers ----------------
__device__ __forceinline__ float f2tf(float x) {
    uint32_t u;
    asm("cvt.rna.tf32.f32 %0, %1;" : "=r"(u) : "f"(x));
    return __uint_as_float(u);
}
__device__ __forceinline__ void mma8(float* d, uint32_t a0, uint32_t a1,
                                     uint32_t a2, uint32_t a3,
                                     uint32_t b0, uint32_t b1) {
    asm volatile(
        "mma.sync.aligned.m16n8k8.row.col.f32.tf32.tf32.f32 "
        "{%0,%1,%2,%3},{%4,%5,%6,%7},{%8,%9},{%0,%1,%2,%3};"
        : "+f"(d[0]), "+f"(d[1]), "+f"(d[2]), "+f"(d[3])
        : "r"(a0), "r"(a1), "r"(a2), "r"(a3), "r"(b0), "r"(b1));
}
// permute k within a kstep-of-8 so pairs (k, k+4) are adjacent -> v2 frag loads
__device__ __forceinline__ int permcol(int k) {
    return (k & ~7) | (((k & 3) << 1) | ((k >> 2) & 1));
}

// ============ GEMM: C[M,1024] = A[M,1024] @ W[1024,1024]^T + bias ============
// 128x128 CTA tile, 128 threads (4 warps of 64x64), 2 CTAs/SM, K-chunk 32.
#define AST 38
__global__ __launch_bounds__(128, 2) void gemm_tc(
    const float* __restrict__ A, const float* __restrict__ W,
    const float* __restrict__ bias, float* __restrict__ C)
{
    __shared__ float As[128 * AST];
    __shared__ float Ws[128 * AST];

    const int tid = threadIdx.x;
    const int lane = tid & 31;
    const int w = tid >> 5;
    const int wm = w >> 1, wn = w & 1;
    const int m0 = blockIdx.y * 128;
    const int n0 = blockIdx.x * 128;
    const int qr = lane >> 2;
    const int qc = 2 * (lane & 3);

    const float* Ap = A + (size_t)(m0 + tid) * EE;
    const float* Wp = W + (size_t)(n0 + tid) * EE;

    float4 ra[8], rw[8];
#pragma unroll
    for (int i = 0; i < 8; i++) {
        ra[i] = *(const float4*)(Ap + i * 4);
        rw[i] = *(const float4*)(Wp + i * 4);
    }

    float acc[4][8][4];
#pragma unroll
    for (int mi = 0; mi < 4; mi++)
#pragma unroll
        for (int ni = 0; ni < 8; ni++)
#pragma unroll
            for (int e = 0; e < 4; e++) acc[mi][ni][e] = 0.0f;

    for (int kc = 0; kc < 32; kc++) {
        __syncthreads();
#pragma unroll
        for (int i = 0; i < 8; i++) {
            float va[4] = {ra[i].x, ra[i].y, ra[i].z, ra[i].w};
            float vw[4] = {rw[i].x, rw[i].y, rw[i].z, rw[i].w};
#pragma unroll
            for (int e = 0; e < 4; e++) {
                int col = permcol(i * 4 + e);
                As[tid * AST + col] = f2tf(va[e]);
                Ws[tid * AST + col] = f2tf(vw[e]);
            }
        }
        __syncthreads();
        if (kc < 31) {
#pragma unroll
            for (int i = 0; i < 8; i++) {
                ra[i] = *(const float4*)(Ap + (kc + 1) * 32 + i * 4);
                rw[i] = *(const float4*)(Wp + (kc + 1) * 32 + i * 4);
            }
        }
#pragma unroll
        for (int ks = 0; ks < 4; ks++) {
            uint32_t af[4][4];
#pragma unroll
            for (int mi = 0; mi < 4; mi++) {
                int r = wm * 64 + mi * 16 + qr;
                float2 lo = *(const float2*)&As[r * AST + ks * 8 + qc];
                float2 hi = *(const float2*)&As[(r + 8) * AST + ks * 8 + qc];
                af[mi][0] = __float_as_uint(lo.x);
                af[mi][1] = __float_as_uint(hi.x);
                af[mi][2] = __float_as_uint(lo.y);
                af[mi][3] = __float_as_uint(hi.y);
            }
#pragma unroll
            for (int ni = 0; ni < 8; ni++) {
                float2 bb = *(const float2*)&Ws[(wn * 64 + ni * 8 + qr) * AST + ks * 8 + qc];
                uint32_t b0 = __float_as_uint(bb.x), b1 = __float_as_uint(bb.y);
#pragma unroll
                for (int mi = 0; mi < 4; mi++)
                    mma8(acc[mi][ni], af[mi][0], af[mi][1], af[mi][2], af[mi][3], b0, b1);
            }
        }
    }

#pragma unroll
    for (int mi = 0; mi < 4; mi++) {
        int rl = m0 + wm * 64 + mi * 16 + qr;
#pragma unroll
        for (int ni = 0; ni < 8; ni++) {
            int cc = n0 + wn * 64 + ni * 8 + qc;
            float2 bv = *(const float2*)&bias[cc];
            *(float2*)&C[(size_t)rl * EE + cc] =
                make_float2(acc[mi][ni][0] + bv.x, acc[mi][ni][1] + bv.y);
            *(float2*)&C[(size_t)(rl + 8) * EE + cc] =
                make_float2(acc[mi][ni][2] + bv.x, acc[mi][ni][3] + bv.y);
        }
    }
}

// ============ Attention (tf32 mma, m=0, register P, fused normalization) ============
// CTA: 128 q-rows, 256 threads (8 warps): wq = w>>1, wk = w&1.
// S phase:  warp tile 32q x 64k  (2 mi x 8 ni)
// PV phase: P in registers; warp tile 32q x 64d over own 64-k half.
// Tail: re-read this CTA's p block (mostly L2-warm) and scale by 1/l in place.
#define QST 68
#define VST 132
#define ATT_DYN ((128 * QST + 128 * QST + 64 * VST + 256) * 4)

__global__ __launch_bounds__(256, 1) void attn_tc(
    const int* __restrict__ mask, float* __restrict__ attn_out)
{
    extern __shared__ float sm[];
    float* Qs = sm;                     // [128][QST]; reused as Osm in epilogue
    float* Ks = Qs + 128 * QST;         // [128][QST] (64 cols used)
    float* Vt = Ks + 128 * QST;         // [64 d][VST k]
    float* lred = Vt + 64 * VST;        // [2][128]

    const int tid = threadIdx.x;
    const int lane = tid & 31;
    const int w = tid >> 5;
    const int qr = lane >> 2;
    const int qc = 2 * (lane & 3);
    const int wq = w >> 1;
    const int wk = w & 1;
    const int qb = wq * 32;

    const int q0 = blockIdx.x * 128;
    const int h = blockIdx.y;
    const int b = blockIdx.z;

    // ---- load Q tile [128 x 64] into perm layout ----
    {
        const int r = tid >> 1;
        const int dh = (tid & 1) * 32;
        const float* Qg = g_Q + (size_t)(b * LQn + q0 + r) * EE + h * DD + dh;
#pragma unroll
        for (int i = 0; i < 8; i++) {
            float4 v = *(const float4*)(Qg + i * 4);
            float va[4] = {v.x, v.y, v.z, v.w};
#pragma unroll
            for (int e = 0; e < 4; e++)
                Qs[r * QST + permcol(dh + i * 4 + e)] = f2tf(va[e]);
        }
    }

    const int r = tid >> 1;
    const int dh = (tid & 1) * 32;
    const float* Kg0 = g_K + (size_t)(b * LKn + r) * EE + h * DD + dh;
    const float* Vg0 = g_V + (size_t)(b * LKn + r) * EE + h * DD + dh;

    float oacc[2][8][4];
#pragma unroll
    for (int mi = 0; mi < 2; mi++)
#pragma unroll
        for (int ni = 0; ni < 8; ni++)
#pragma unroll
            for (int e = 0; e < 4; e++) oacc[mi][ni][e] = 0.0f;

    float lacc[2][2] = {{0.0f, 0.0f}, {0.0f, 0.0f}};

    const int* mptr[2][2];
    float* optr[2][2];
#pragma unroll
    for (int mi = 0; mi < 2; mi++)
#pragma unroll
        for (int hi = 0; hi < 2; hi++) {
            int q = q0 + qb + mi * 16 + hi * 8 + qr;
            mptr[mi][hi] = mask + ((size_t)b * LQn + q) * LKn + wk * 64;
            optr[mi][hi] = attn_out + ((size_t)(b * HH + h) * LQn + q) * LKn + wk * 64;
        }

    for (int c = 0; c < 16; c++) {
        __syncthreads();  // previous-iteration Ks/Vt reads complete
        const float* Kg = Kg0 + (size_t)c * 128 * EE;
        const float* Vg = Vg0 + (size_t)c * 128 * EE;
#pragma unroll
        for (int i = 0; i < 8; i++) {
            float4 kv = *(const float4*)(Kg + i * 4);
            float4 vv = *(const float4*)(Vg + i * 4);
            float vk[4] = {kv.x, kv.y, kv.z, kv.w};
            float vvv[4] = {vv.x, vv.y, vv.z, vv.w};
#pragma unroll
            for (int e = 0; e < 4; e++) {
                int d = dh + i * 4 + e;
                Ks[r * QST + permcol(d)] = f2tf(vk[e]);
                Vt[d * VST + r] = f2tf(vvv[e]);
            }
        }
        __syncthreads();

        // ---- S = Q @ K^T : warp tile 32q x 64k ----
        float sacc[2][8][4];
#pragma unroll
        for (int mi = 0; mi < 2; mi++)
#pragma unroll
            for (int ni = 0; ni < 8; ni++)
#pragma unroll
                for (int e = 0; e < 4; e++) sacc[mi][ni][e] = 0.0f;

#pragma unroll
        for (int ks = 0; ks < 8; ks++) {
            uint32_t af[2][4];
#pragma unroll
            for (int mi = 0; mi < 2; mi++) {
                int ar = qb + mi * 16 + qr;
                float2 lo = *(const float2*)&Qs[ar * QST + ks * 8 + qc];
                float2 hi = *(const float2*)&Qs[(ar + 8) * QST + ks * 8 + qc];
                af[mi][0] = __float_as_uint(lo.x);
                af[mi][1] = __float_as_uint(hi.x);
                af[mi][2] = __float_as_uint(lo.y);
                af[mi][3] = __float_as_uint(hi.y);
            }
#pragma unroll
            for (int ni = 0; ni < 8; ni++) {
                float2 bb = *(const float2*)&Ks[(wk * 64 + ni * 8 + qr) * QST + ks * 8 + qc];
                uint32_t b0 = __float_as_uint(bb.x), b1 = __float_as_uint(bb.y);
#pragma unroll
                for (int mi = 0; mi < 2; mi++)
                    mma8(sacc[mi][ni], af[mi][0], af[mi][1], af[mi][2], af[mi][3], b0, b1);
            }
        }

        // ---- softmax (m=0): mask, p=exp, store p to gmem; p stays in regs ----
#pragma unroll
        for (int mi = 0; mi < 2; mi++) {
#pragma unroll
            for (int ni = 0; ni < 8; ni++) {
                int cb = ni * 8 + qc;
                int2 m2lo = *(const int2*)(mptr[mi][0] + c * 128 + cb);
                int2 m2hi = *(const int2*)(mptr[mi][1] + c * 128 + cb);
                float s0 = sacc[mi][ni][0] * 0.125f; if (m2lo.x == 0) s0 = -1.0e30f;
                float s1 = sacc[mi][ni][1] * 0.125f; if (m2lo.y == 0) s1 = -1.0e30f;
                float s2 = sacc[mi][ni][2] * 0.125f; if (m2hi.x == 0) s2 = -1.0e30f;
                float s3 = sacc[mi][ni][3] * 0.125f; if (m2hi.y == 0) s3 = -1.0e30f;
                float p0 = __expf(s0), p1 = __expf(s1);
                float p2 = __expf(s2), p3 = __expf(s3);
                *(float2*)(optr[mi][0] + c * 128 + cb) = make_float2(p0, p1);
                *(float2*)(optr[mi][1] + c * 128 + cb) = make_float2(p2, p3);
                lacc[mi][0] += p0 + p1;
                lacc[mi][1] += p2 + p3;
                sacc[mi][ni][0] = f2tf(p0);
                sacc[mi][ni][1] = f2tf(p1);
                sacc[mi][ni][2] = f2tf(p2);
                sacc[mi][ni][3] = f2tf(p3);
            }
        }

        // ---- O += P @ V : P from registers (C-frag == A-frag via V slot layout) ----
#pragma unroll
        for (int ks = 0; ks < 8; ks++) {
            uint32_t a0[2], a1[2], a2[2], a3[2];
#pragma unroll
            for (int mi = 0; mi < 2; mi++) {
                a0[mi] = __float_as_uint(sacc[mi][ks][0]);
                a1[mi] = __float_as_uint(sacc[mi][ks][2]);
                a2[mi] = __float_as_uint(sacc[mi][ks][1]);
                a3[mi] = __float_as_uint(sacc[mi][ks][3]);
            }
#pragma unroll
            for (int ni = 0; ni < 8; ni++) {
                float2 bb = *(const float2*)&Vt[(ni * 8 + qr) * VST + wk * 64 + ks * 8 + qc];
                uint32_t b0 = __float_as_uint(bb.x), b1 = __float_as_uint(bb.y);
#pragma unroll
                for (int mi = 0; mi < 2; mi++)
                    mma8(oacc[mi][ni], a0[mi], a1[mi], a2[mi], a3[mi], b0, b1);
            }
        }
    }

    // ---- epilogue: reduce l (quad + wk) and O (across wk) ----
#pragma unroll
    for (int mi = 0; mi < 2; mi++)
#pragma unroll
        for (int hi = 0; hi < 2; hi++) {
            float v = lacc[mi][hi];
            v += __shfl_xor_sync(0xFFFFFFFF, v, 1);
            v += __shfl_xor_sync(0xFFFFFFFF, v, 2);
            if ((lane & 3) == 0)
                lred[wk * 128 + qb + mi * 16 + hi * 8 + qr] = v;
        }
    __syncthreads();  // lred ready; all main-loop smem reads done

    float* Osm = Qs;  // reuse Q smem
    if (wk == 1) {
#pragma unroll
        for (int mi = 0; mi < 2; mi++) {
            int row = qb + mi * 16 + qr;
#pragma unroll
            for (int ni = 0; ni < 8; ni++) {
                *(float2*)&Osm[row * QST + ni * 8 + qc] =
                    make_float2(oacc[mi][ni][0], oacc[mi][ni][1]);
                *(float2*)&Osm[(row + 8) * QST + ni * 8 + qc] =
                    make_float2(oacc[mi][ni][2], oacc[mi][ni][3]);
            }
        }
    }
    __syncthreads();

    if (wk == 0) {
#pragma unroll
        for (int mi = 0; mi < 2; mi++) {
#pragma unroll
            for (int hi = 0; hi < 2; hi++) {
                int rrow = qb + mi * 16 + hi * 8 + qr;
                float l = lred[rrow] + lred[128 + rrow];
                float inv = 1.0f / l;
                float* og = g_ctx + (size_t)(b * LQn + q0 + rrow) * EE + h * DD;
#pragma unroll
                for (int ni = 0; ni < 8; ni++) {
                    float2 part = *(const float2*)&Osm[rrow * QST + ni * 8 + qc];
                    *(float2*)(og + ni * 8 + qc) = make_float2(
                        (oacc[mi][ni][hi * 2 + 0] + part.x) * inv,
                        (oacc[mi][ni][hi * 2 + 1] + part.y) * inv);
                }
            }
        }
    }

    // ---- fused normalization: scale this CTA's p block by 1/l in place ----
    // thread -> row = tid>>1 (0..127), half = tid&1 (cols half*1024..+1023)
    {
        const int nrow = tid >> 1;
        const int nhalf = tid & 1;
        const float inv = 1.0f / (lred[nrow] + lred[128 + nrow]);
        float4* prow = (float4*)(attn_out +
            ((size_t)(b * HH + h) * LQn + q0 + nrow) * LKn + nhalf * 1024);
#pragma unroll 8
        for (int i = 0; i < 256; i++) {
            float4 v = prow[i];
            v.x *= inv; v.y *= inv; v.z *= inv; v.w *= inv;
            prow[i] = v;
        }
    }
}

// ---------------- launch ----------------
extern "C" void kernel_launch(void* const* d_in, const int* in_sizes, int n_in,
                              void* d_out, int out_size)
{
    const float* q_in = (const float*)d_in[0];
    const float* k_in = (const float*)d_in[1];
    const float* v_in = (const float*)d_in[2];
    const int*   mask = (const int*)d_in[3];
    const float* Wq = (const float*)d_in[4];
    const float* bq = (const float*)d_in[5];
    const float* Wk = (const float*)d_in[6];
    const float* bk = (const float*)d_in[7];
    const float* Wv = (const float*)d_in[8];
    const float* bv = (const float*)d_in[9];
    const float* Wo = (const float*)d_in[10];
    const float* bo = (const float*)d_in[11];

    float* out = (float*)d_out;

    float *gQ, *gK, *gV, *gctx, *gSraw;
    cudaGetSymbolAddress((void**)&gQ, g_Q);
    cudaGetSymbolAddress((void**)&gK, g_K);
    cudaGetSymbolAddress((void**)&gV, g_V);
    cudaGetSymbolAddress((void**)&gctx, g_ctx);
    cudaGetSymbolAddress((void**)&gSraw, g_Sraw);

    const size_t OUT_ELEMS = (size_t)BB * LQn * EE;
    const size_t ATT_ELEMS = (size_t)BB * HH * LQn * LKn;
    bool attn_is_output = ((size_t)out_size >= OUT_ELEMS + ATT_ELEMS);
    float* attnp = attn_is_output ? (out + OUT_ELEMS) : gSraw;

    cudaFuncSetAttribute(attn_tc, cudaFuncAttributeMaxDynamicSharedMemorySize, ATT_DYN);

    dim3 gemmGrid(8, 32);
    gemm_tc<<<gemmGrid, 128>>>(q_in, Wq, bq, gQ);
    gemm_tc<<<gemmGrid, 128>>>(k_in, Wk, bk, gK);
    gemm_tc<<<gemmGrid, 128>>>(v_in, Wv, bv, gV);

    dim3 attnGrid(LQn / 128, HH, BB);  // (16, 16, 2)
    attn_tc<<<attnGrid, 256, ATT_DYN>>>(mask, attnp);

    gemm_tc<<<gemmGrid, 128>>>(gctx, Wo, bo, out);
}

// round 8
// speedup vs baseline: 1.3315x; 1.3315x over previous
#include <cuda_runtime.h>
#include <cuda_fp16.h>
#include <math.h>
#include <stdint.h>

#define BB 2
#define LQn 2048
#define LKn 2048
#define EE 1024
#define HH 16
#define DD 64

// ---------------- scratch ----------------
__device__ float g_Q[(size_t)BB * LQn * EE];
__device__ float g_K[(size_t)BB * LKn * EE];
__device__ float g_V[(size_t)BB * LKn * EE];
__device__ float g_ctx[(size_t)BB * LQn * EE];
__device__ float g_stats[(size_t)BB * HH * LQn];
__device__ float g_Sraw[(size_t)BB * HH * LQn * LKn];

// ---------------- helpers ----------------
__device__ __forceinline__ uint32_t h2(float x, float y) {
    __half2 h = __floats2half2_rn(x, y);
    return *(uint32_t*)&h;
}
__device__ __forceinline__ void mma16(float* d, uint32_t a0, uint32_t a1,
                                      uint32_t a2, uint32_t a3,
                                      uint32_t b0, uint32_t b1) {
    asm volatile(
        "mma.sync.aligned.m16n8k16.row.col.f32.f16.f16.f32 "
        "{%0,%1,%2,%3},{%4,%5,%6,%7},{%8,%9},{%0,%1,%2,%3};"
        : "+f"(d[0]), "+f"(d[1]), "+f"(d[2]), "+f"(d[3])
        : "r"(a0), "r"(a1), "r"(a2), "r"(a3), "r"(b0), "r"(b1));
}
// permute unit index within a kstep-of-8 units so (u, u+4) become adjacent
__device__ __forceinline__ int permu(int x) {
    return ((x & 3) << 1) | ((x >> 2) & 1);
}
__device__ __forceinline__ int permU(int U) {  // general: keep kstep group
    return (U & ~7) | permu(U & 7);
}

// ============ GEMM: C[M,1024] = A[M,1024] @ W[1024,1024]^T + bias (f16 mma) ============
// 128x128 CTA tile, 128 threads (4 warps of 64x64), K-chunk 32 (2 ksteps of 16).
#define ASTH 18
__global__ __launch_bounds__(128, 2) void gemm_tc(
    const float* __restrict__ A, const float* __restrict__ W,
    const float* __restrict__ bias, float* __restrict__ C)
{
    __shared__ uint32_t As[128 * ASTH];
    __shared__ uint32_t Ws[128 * ASTH];

    const int tid = threadIdx.x;
    const int lane = tid & 31;
    const int w = tid >> 5;
    const int wm = w >> 1, wn = w & 1;
    const int m0 = blockIdx.y * 128;
    const int n0 = blockIdx.x * 128;
    const int qr = lane >> 2;
    const int qc = 2 * (lane & 3);

    const float* Ap = A + (size_t)(m0 + tid) * EE;
    const float* Wp = W + (size_t)(n0 + tid) * EE;

    float4 ra[8], rw[8];
#pragma unroll
    for (int i = 0; i < 8; i++) {
        ra[i] = *(const float4*)(Ap + i * 4);
        rw[i] = *(const float4*)(Wp + i * 4);
    }

    float acc[4][8][4];
#pragma unroll
    for (int mi = 0; mi < 4; mi++)
#pragma unroll
        for (int ni = 0; ni < 8; ni++)
#pragma unroll
            for (int e = 0; e < 4; e++) acc[mi][ni][e] = 0.0f;

    for (int kc = 0; kc < 32; kc++) {
        __syncthreads();
#pragma unroll
        for (int i = 0; i < 8; i++) {
            As[tid * ASTH + permU(2 * i)]     = h2(ra[i].x, ra[i].y);
            As[tid * ASTH + permU(2 * i + 1)] = h2(ra[i].z, ra[i].w);
            Ws[tid * ASTH + permU(2 * i)]     = h2(rw[i].x, rw[i].y);
            Ws[tid * ASTH + permU(2 * i + 1)] = h2(rw[i].z, rw[i].w);
        }
        __syncthreads();
        if (kc < 31) {
#pragma unroll
            for (int i = 0; i < 8; i++) {
                ra[i] = *(const float4*)(Ap + (kc + 1) * 32 + i * 4);
                rw[i] = *(const float4*)(Wp + (kc + 1) * 32 + i * 4);
            }
        }
#pragma unroll
        for (int ks = 0; ks < 2; ks++) {
            uint32_t af[4][4];
#pragma unroll
            for (int mi = 0; mi < 4; mi++) {
                int r = wm * 64 + mi * 16 + qr;
                uint2 lo = *(const uint2*)&As[r * ASTH + ks * 8 + qc];
                uint2 hi = *(const uint2*)&As[(r + 8) * ASTH + ks * 8 + qc];
                af[mi][0] = lo.x; af[mi][1] = hi.x;
                af[mi][2] = lo.y; af[mi][3] = hi.y;
            }
#pragma unroll
            for (int ni = 0; ni < 8; ni++) {
                uint2 bb = *(const uint2*)&Ws[(wn * 64 + ni * 8 + qr) * ASTH + ks * 8 + qc];
#pragma unroll
                for (int mi = 0; mi < 4; mi++)
                    mma16(acc[mi][ni], af[mi][0], af[mi][1], af[mi][2], af[mi][3],
                          bb.x, bb.y);
            }
        }
    }

#pragma unroll
    for (int mi = 0; mi < 4; mi++) {
        int rl = m0 + wm * 64 + mi * 16 + qr;
#pragma unroll
        for (int ni = 0; ni < 8; ni++) {
            int cc = n0 + wn * 64 + ni * 8 + qc;
            float2 bv = *(const float2*)&bias[cc];
            *(float2*)&C[(size_t)rl * EE + cc] =
                make_float2(acc[mi][ni][0] + bv.x, acc[mi][ni][1] + bv.y);
            *(float2*)&C[(size_t)(rl + 8) * EE + cc] =
                make_float2(acc[mi][ni][2] + bv.x, acc[mi][ni][3] + bv.y);
        }
    }
}

// ============ Attention (f16 mma, fixed max m=0, register-resident P) ============
// CTA: 128 q-rows, 256 threads (8 warps): wq = w>>1, wk = w&1.
// S phase:  warp tile 32q x 64k  (2 mi x 8 ni, 4 ksteps of 16 over d=64)
// PV phase: P in registers (S C-frag pairs -> f16 A-frags), warp tile
//           32q x 64d over own 64-k half (4 ksteps of 16).
#define QSTH 36
#define VSTH 68
#define ATT_DYN ((128 * QSTH + 128 * QSTH + 64 * VSTH + 256) * 4)

__global__ __launch_bounds__(256, 1) void attn_tc(
    const int* __restrict__ mask, float* __restrict__ attn_out)
{
    extern __shared__ uint32_t smu[];
    uint32_t* Qs = smu;                     // [128][QSTH] half2 units
    uint32_t* Ks = Qs + 128 * QSTH;         // [128][QSTH]
    uint32_t* Vt = Ks + 128 * QSTH;         // [64 d][VSTH k-units]
    float* lred = (float*)(Vt + 64 * VSTH); // [2][128]
    float* Osm = (float*)smu;               // epilogue reuse (stride 68, 128 rows)

    const int tid = threadIdx.x;
    const int lane = tid & 31;
    const int w = tid >> 5;
    const int qr = lane >> 2;
    const int qc = 2 * (lane & 3);
    const int wq = w >> 1;
    const int wk = w & 1;
    const int qb = wq * 32;

    const int q0 = blockIdx.x * 128;
    const int h = blockIdx.y;
    const int b = blockIdx.z;

    // ---- load Q tile [128 x 64] into perm half2 layout ----
    {
        const int r = tid >> 1;
        const int dh = (tid & 1) * 32;
        const int ub = dh >> 1;  // 0 or 16
        const float* Qg = g_Q + (size_t)(b * LQn + q0 + r) * EE + h * DD + dh;
#pragma unroll
        for (int i = 0; i < 8; i++) {
            float4 v = *(const float4*)(Qg + i * 4);
            Qs[r * QSTH + permU(ub + 2 * i)]     = h2(v.x, v.y);
            Qs[r * QSTH + permU(ub + 2 * i + 1)] = h2(v.z, v.w);
        }
    }

    const int r = tid >> 1;
    const int dh = (tid & 1) * 32;
    const int ub = dh >> 1;
    const float* Kg0 = g_K + (size_t)(b * LKn + r) * EE + h * DD + dh;
    const float* Vg0 = g_V + (size_t)(b * LKn + r) * EE + h * DD + dh;
    const int vunit = permU(r >> 1);  // Vt unit position for this k-row
    const int vbyte = (r & 1) * 2;    // half slot within the unit

    float oacc[2][8][4];
#pragma unroll
    for (int mi = 0; mi < 2; mi++)
#pragma unroll
        for (int ni = 0; ni < 8; ni++)
#pragma unroll
            for (int e = 0; e < 4; e++) oacc[mi][ni][e] = 0.0f;

    float lacc[2][2] = {{0.0f, 0.0f}, {0.0f, 0.0f}};

    const int* mptr[2][2];
    float* optr[2][2];
#pragma unroll
    for (int mi = 0; mi < 2; mi++)
#pragma unroll
        for (int hi = 0; hi < 2; hi++) {
            int q = q0 + qb + mi * 16 + hi * 8 + qr;
            mptr[mi][hi] = mask + ((size_t)b * LQn + q) * LKn + wk * 64;
            optr[mi][hi] = attn_out + ((size_t)(b * HH + h) * LQn + q) * LKn + wk * 64;
        }

    for (int c = 0; c < 16; c++) {
        __syncthreads();  // previous-iteration Ks/Vt reads complete
        const float* Kg = Kg0 + (size_t)c * 128 * EE;
        const float* Vg = Vg0 + (size_t)c * 128 * EE;
#pragma unroll
        for (int i = 0; i < 8; i++) {
            float4 kv = *(const float4*)(Kg + i * 4);
            float4 vv = *(const float4*)(Vg + i * 4);
            Ks[r * QSTH + permU(ub + 2 * i)]     = h2(kv.x, kv.y);
            Ks[r * QSTH + permU(ub + 2 * i + 1)] = h2(kv.z, kv.w);
            // V transposed: d-row, k-unit column (half stores)
            float vvv[4] = {vv.x, vv.y, vv.z, vv.w};
#pragma unroll
            for (int e = 0; e < 4; e++) {
                int d = dh + i * 4 + e;
                *(__half*)((char*)(Vt + d * VSTH + vunit) + vbyte) =
                    __float2half_rn(vvv[e]);
            }
        }
        __syncthreads();

        // ---- S = Q @ K^T : warp tile 32q x 64k, 4 ksteps of 16 ----
        float sacc[2][8][4];
#pragma unroll
        for (int mi = 0; mi < 2; mi++)
#pragma unroll
            for (int ni = 0; ni < 8; ni++)
#pragma unroll
                for (int e = 0; e < 4; e++) sacc[mi][ni][e] = 0.0f;

#pragma unroll
        for (int ks = 0; ks < 4; ks++) {
            uint32_t af[2][4];
#pragma unroll
            for (int mi = 0; mi < 2; mi++) {
                int ar = qb + mi * 16 + qr;
                uint2 lo = *(const uint2*)&Qs[ar * QSTH + ks * 8 + qc];
                uint2 hi = *(const uint2*)&Qs[(ar + 8) * QSTH + ks * 8 + qc];
                af[mi][0] = lo.x; af[mi][1] = hi.x;
                af[mi][2] = lo.y; af[mi][3] = hi.y;
            }
#pragma unroll
            for (int ni = 0; ni < 8; ni++) {
                uint2 bb = *(const uint2*)&Ks[(wk * 64 + ni * 8 + qr) * QSTH + ks * 8 + qc];
#pragma unroll
                for (int mi = 0; mi < 2; mi++)
                    mma16(sacc[mi][ni], af[mi][0], af[mi][1], af[mi][2], af[mi][3],
                          bb.x, bb.y);
            }
        }

        // ---- softmax (m=0): mask, p=exp, store p to gmem; p stays in regs ----
#pragma unroll
        for (int mi = 0; mi < 2; mi++) {
#pragma unroll
            for (int ni = 0; ni < 8; ni++) {
                int cb = ni * 8 + qc;
                int2 m2lo = *(const int2*)(mptr[mi][0] + c * 128 + cb);
                int2 m2hi = *(const int2*)(mptr[mi][1] + c * 128 + cb);
                float s0 = sacc[mi][ni][0] * 0.125f; if (m2lo.x == 0) s0 = -1.0e30f;
                float s1 = sacc[mi][ni][1] * 0.125f; if (m2lo.y == 0) s1 = -1.0e30f;
                float s2 = sacc[mi][ni][2] * 0.125f; if (m2hi.x == 0) s2 = -1.0e30f;
                float s3 = sacc[mi][ni][3] * 0.125f; if (m2hi.y == 0) s3 = -1.0e30f;
                float p0 = __expf(s0), p1 = __expf(s1);
                float p2 = __expf(s2), p3 = __expf(s3);
                *(float2*)(optr[mi][0] + c * 128 + cb) = make_float2(p0, p1);
                *(float2*)(optr[mi][1] + c * 128 + cb) = make_float2(p2, p3);
                lacc[mi][0] += p0 + p1;
                lacc[mi][1] += p2 + p3;
                sacc[mi][ni][0] = p0; sacc[mi][ni][1] = p1;
                sacc[mi][ni][2] = p2; sacc[mi][ni][3] = p3;
            }
        }

        // ---- O += P @ V : f16 A-frags packed from S C-frag pairs ----
#pragma unroll
        for (int j = 0; j < 4; j++) {  // ksteps of 16 over own 64-k half
            uint32_t a0[2], a1[2], a2[2], a3[2];
#pragma unroll
            for (int mi = 0; mi < 2; mi++) {
                a0[mi] = h2(sacc[mi][2 * j][0], sacc[mi][2 * j][1]);
                a1[mi] = h2(sacc[mi][2 * j][2], sacc[mi][2 * j][3]);
                a2[mi] = h2(sacc[mi][2 * j + 1][0], sacc[mi][2 * j + 1][1]);
                a3[mi] = h2(sacc[mi][2 * j + 1][2], sacc[mi][2 * j + 1][3]);
            }
#pragma unroll
            for (int ni = 0; ni < 8; ni++) {
                uint2 bb = *(const uint2*)&Vt[(ni * 8 + qr) * VSTH + wk * 32 + j * 8 + qc];
#pragma unroll
                for (int mi = 0; mi < 2; mi++)
                    mma16(oacc[mi][ni], a0[mi], a1[mi], a2[mi], a3[mi], bb.x, bb.y);
            }
        }
    }

    // ---- epilogue: reduce l (quad + wk) and O (across wk) ----
#pragma unroll
    for (int mi = 0; mi < 2; mi++)
#pragma unroll
        for (int hi = 0; hi < 2; hi++) {
            float v = lacc[mi][hi];
            v += __shfl_xor_sync(0xFFFFFFFF, v, 1);
            v += __shfl_xor_sync(0xFFFFFFFF, v, 2);
            if ((lane & 3) == 0)
                lred[wk * 128 + qb + mi * 16 + hi * 8 + qr] = v;
        }
    __syncthreads();

    if (wk == 1) {
#pragma unroll
        for (int mi = 0; mi < 2; mi++) {
            int row = qb + mi * 16 + qr;
#pragma unroll
            for (int ni = 0; ni < 8; ni++) {
                *(float2*)&Osm[row * 68 + ni * 8 + qc] =
                    make_float2(oacc[mi][ni][0], oacc[mi][ni][1]);
                *(float2*)&Osm[(row + 8) * 68 + ni * 8 + qc] =
                    make_float2(oacc[mi][ni][2], oacc[mi][ni][3]);
            }
        }
    }
    __syncthreads();

    if (wk == 0) {
#pragma unroll
        for (int mi = 0; mi < 2; mi++) {
#pragma unroll
            for (int hi = 0; hi < 2; hi++) {
                int rrow = qb + mi * 16 + hi * 8 + qr;
                float l = lred[rrow] + lred[128 + rrow];
                float inv = 1.0f / l;
                float* og = g_ctx + (size_t)(b * LQn + q0 + rrow) * EE + h * DD;
#pragma unroll
                for (int ni = 0; ni < 8; ni++) {
                    float2 part = *(const float2*)&Osm[rrow * 68 + ni * 8 + qc];
                    *(float2*)(og + ni * 8 + qc) = make_float2(
                        (oacc[mi][ni][hi * 2 + 0] + part.x) * inv,
                        (oacc[mi][ni][hi * 2 + 1] + part.y) * inv);
                }
                if ((lane & 3) == 0)
                    g_stats[(size_t)(b * HH + h) * LQn + q0 + rrow] = l;
            }
        }
    }
}

// ---------------- normalize: attn = p / l ----------------
__global__ __launch_bounds__(256) void attn_norm(float* __restrict__ attn)
{
    size_t i4 = (size_t)blockIdx.x * blockDim.x + threadIdx.x;
    const size_t total4 = (size_t)BB * HH * LQn * LKn / 4;
    if (i4 >= total4) return;
    size_t row = (i4 * 4) >> 11;
    float invl = 1.0f / g_stats[row];
    float4 s = ((float4*)attn)[i4];
    s.x *= invl; s.y *= invl; s.z *= invl; s.w *= invl;
    ((float4*)attn)[i4] = s;
}

// ---------------- launch ----------------
extern "C" void kernel_launch(void* const* d_in, const int* in_sizes, int n_in,
                              void* d_out, int out_size)
{
    const float* q_in = (const float*)d_in[0];
    const float* k_in = (const float*)d_in[1];
    const float* v_in = (const float*)d_in[2];
    const int*   mask = (const int*)d_in[3];
    const float* Wq = (const float*)d_in[4];
    const float* bq = (const float*)d_in[5];
    const float* Wk = (const float*)d_in[6];
    const float* bk = (const float*)d_in[7];
    const float* Wv = (const float*)d_in[8];
    const float* bv = (const float*)d_in[9];
    const float* Wo = (const float*)d_in[10];
    const float* bo = (const float*)d_in[11];

    float* out = (float*)d_out;

    float *gQ, *gK, *gV, *gctx, *gSraw;
    cudaGetSymbolAddress((void**)&gQ, g_Q);
    cudaGetSymbolAddress((void**)&gK, g_K);
    cudaGetSymbolAddress((void**)&gV, g_V);
    cudaGetSymbolAddress((void**)&gctx, g_ctx);
    cudaGetSymbolAddress((void**)&gSraw, g_Sraw);

    const size_t OUT_ELEMS = (size_t)BB * LQn * EE;
    const size_t ATT_ELEMS = (size_t)BB * HH * LQn * LKn;
    bool attn_is_output = ((size_t)out_size >= OUT_ELEMS + ATT_ELEMS);
    float* attnp = attn_is_output ? (out + OUT_ELEMS) : gSraw;

    cudaFuncSetAttribute(attn_tc, cudaFuncAttributeMaxDynamicSharedMemorySize, ATT_DYN);

    dim3 gemmGrid(8, 32);
    gemm_tc<<<gemmGrid, 128>>>(q_in, Wq, bq, gQ);
    gemm_tc<<<gemmGrid, 128>>>(k_in, Wk, bk, gK);
    gemm_tc<<<gemmGrid, 128>>>(v_in, Wv, bv, gV);

    dim3 attnGrid(LQn / 128, HH, BB);  // (16, 16, 2)
    attn_tc<<<attnGrid, 256, ATT_DYN>>>(mask, attnp);

    gemm_tc<<<gemmGrid, 128>>>(gctx, Wo, bo, out);

    if (attn_is_output) {
        size_t total4 = ATT_ELEMS / 4;
        int blocks = (int)((total4 + 255) / 256);
        attn_norm<<<blocks, 256>>>(attnp);
    }
}

// round 9
// speedup vs baseline: 1.5771x; 1.1845x over previous
#include <cuda_runtime.h>
#include <cuda_fp16.h>
#include <math.h>
#include <stdint.h>

#define BB 2
#define LQn 2048
#define LKn 2048
#define EE 1024
#define HH 16
#define DD 64

// ---------------- scratch (f16 activations) ----------------
__device__ __half g_Q[(size_t)BB * LQn * EE];
__device__ __half g_K[(size_t)BB * LKn * EE];
__device__ __half g_V[(size_t)BB * LKn * EE];
__device__ __half g_ctx[(size_t)BB * LQn * EE];
__device__ float g_stats[(size_t)BB * HH * LQn];
__device__ float g_Sraw[(size_t)BB * HH * LQn * LKn];

// ---------------- helpers ----------------
__device__ __forceinline__ uint32_t h2(float x, float y) {
    __half2 h = __floats2half2_rn(x, y);
    return *(uint32_t*)&h;
}
__device__ __forceinline__ void mma16(float* d, uint32_t a0, uint32_t a1,
                                      uint32_t a2, uint32_t a3,
                                      uint32_t b0, uint32_t b1) {
    asm volatile(
        "mma.sync.aligned.m16n8k16.row.col.f32.f16.f16.f32 "
        "{%0,%1,%2,%3},{%4,%5,%6,%7},{%8,%9},{%0,%1,%2,%3};"
        : "+f"(d[0]), "+f"(d[1]), "+f"(d[2]), "+f"(d[3])
        : "r"(a0), "r"(a1), "r"(a2), "r"(a3), "r"(b0), "r"(b1));
}
__device__ __forceinline__ int permu(int x) {
    return ((x & 3) << 1) | ((x >> 2) & 1);
}
__device__ __forceinline__ int permU(int U) {
    return (U & ~7) | permu(U & 7);
}
__device__ __forceinline__ uint32_t smem_u32p(const void* p) {
    uint32_t a;
    asm("{ .reg .u64 t; cvta.to.shared.u64 t, %1; cvt.u32.u64 %0, t; }"
        : "=r"(a) : "l"(p));
    return a;
}
#define LDM4(d0, d1, d2, d3, a)                                            \
    asm volatile("ldmatrix.sync.aligned.m8n8.x4.shared.b16 {%0,%1,%2,%3}, [%4];" \
                 : "=r"(d0), "=r"(d1), "=r"(d2), "=r"(d3) : "r"(a))
#define LDM4T(d0, d1, d2, d3, a)                                           \
    asm volatile("ldmatrix.sync.aligned.m8n8.x4.trans.shared.b16 {%0,%1,%2,%3}, [%4];" \
                 : "=r"(d0), "=r"(d1), "=r"(d2), "=r"(d3) : "r"(a))

// ============ GEMM (f32 in, f16 out): C = A @ W^T + bias ============
#define ASTH 18
__global__ __launch_bounds__(128, 2) void gemm_f(
    const float* __restrict__ A, const float* __restrict__ W,
    const float* __restrict__ bias, __half* __restrict__ C)
{
    __shared__ uint32_t As[128 * ASTH];
    __shared__ uint32_t Ws[128 * ASTH];

    const int tid = threadIdx.x;
    const int lane = tid & 31;
    const int w = tid >> 5;
    const int wm = w >> 1, wn = w & 1;
    const int m0 = blockIdx.y * 128;
    const int n0 = blockIdx.x * 128;
    const int qr = lane >> 2;
    const int qc = 2 * (lane & 3);

    const float* Ap = A + (size_t)(m0 + tid) * EE;
    const float* Wp = W + (size_t)(n0 + tid) * EE;

    float4 ra[8], rw[8];
#pragma unroll
    for (int i = 0; i < 8; i++) {
        ra[i] = *(const float4*)(Ap + i * 4);
        rw[i] = *(const float4*)(Wp + i * 4);
    }

    float acc[4][8][4];
#pragma unroll
    for (int mi = 0; mi < 4; mi++)
#pragma unroll
        for (int ni = 0; ni < 8; ni++)
#pragma unroll
            for (int e = 0; e < 4; e++) acc[mi][ni][e] = 0.0f;

    for (int kc = 0; kc < 32; kc++) {
        __syncthreads();
#pragma unroll
        for (int i = 0; i < 8; i++) {
            As[tid * ASTH + permU(2 * i)]     = h2(ra[i].x, ra[i].y);
            As[tid * ASTH + permU(2 * i + 1)] = h2(ra[i].z, ra[i].w);
            Ws[tid * ASTH + permU(2 * i)]     = h2(rw[i].x, rw[i].y);
            Ws[tid * ASTH + permU(2 * i + 1)] = h2(rw[i].z, rw[i].w);
        }
        __syncthreads();
        if (kc < 31) {
#pragma unroll
            for (int i = 0; i < 8; i++) {
                ra[i] = *(const float4*)(Ap + (kc + 1) * 32 + i * 4);
                rw[i] = *(const float4*)(Wp + (kc + 1) * 32 + i * 4);
            }
        }
#pragma unroll
        for (int ks = 0; ks < 2; ks++) {
            uint32_t af[4][4];
#pragma unroll
            for (int mi = 0; mi < 4; mi++) {
                int r = wm * 64 + mi * 16 + qr;
                uint2 lo = *(const uint2*)&As[r * ASTH + ks * 8 + qc];
                uint2 hi = *(const uint2*)&As[(r + 8) * ASTH + ks * 8 + qc];
                af[mi][0] = lo.x; af[mi][1] = hi.x;
                af[mi][2] = lo.y; af[mi][3] = hi.y;
            }
#pragma unroll
            for (int ni = 0; ni < 8; ni++) {
                uint2 bb = *(const uint2*)&Ws[(wn * 64 + ni * 8 + qr) * ASTH + ks * 8 + qc];
#pragma unroll
                for (int mi = 0; mi < 4; mi++)
                    mma16(acc[mi][ni], af[mi][0], af[mi][1], af[mi][2], af[mi][3],
                          bb.x, bb.y);
            }
        }
    }

#pragma unroll
    for (int mi = 0; mi < 4; mi++) {
        int rl = m0 + wm * 64 + mi * 16 + qr;
#pragma unroll
        for (int ni = 0; ni < 8; ni++) {
            int cc = n0 + wn * 64 + ni * 8 + qc;
            float2 bv = *(const float2*)&bias[cc];
            *(uint32_t*)&C[(size_t)rl * EE + cc] =
                h2(acc[mi][ni][0] + bv.x, acc[mi][ni][1] + bv.y);
            *(uint32_t*)&C[(size_t)(rl + 8) * EE + cc] =
                h2(acc[mi][ni][2] + bv.x, acc[mi][ni][3] + bv.y);
        }
    }
}

// ============ GEMM (f16 in, f32 out): out = ctx @ Wo^T + bo ============
__global__ __launch_bounds__(128, 2) void gemm_out(
    const __half* __restrict__ A, const float* __restrict__ W,
    const float* __restrict__ bias, float* __restrict__ C)
{
    __shared__ uint32_t As[128 * ASTH];
    __shared__ uint32_t Ws[128 * ASTH];

    const int tid = threadIdx.x;
    const int lane = tid & 31;
    const int w = tid >> 5;
    const int wm = w >> 1, wn = w & 1;
    const int m0 = blockIdx.y * 128;
    const int n0 = blockIdx.x * 128;
    const int qr = lane >> 2;
    const int qc = 2 * (lane & 3);

    const __half* Ap = A + (size_t)(m0 + tid) * EE;
    const float* Wp = W + (size_t)(n0 + tid) * EE;

    uint4 ra[4];
    float4 rw[8];
#pragma unroll
    for (int i = 0; i < 4; i++) ra[i] = *(const uint4*)(Ap + i * 8);
#pragma unroll
    for (int i = 0; i < 8; i++) rw[i] = *(const float4*)(Wp + i * 4);

    float acc[4][8][4];
#pragma unroll
    for (int mi = 0; mi < 4; mi++)
#pragma unroll
        for (int ni = 0; ni < 8; ni++)
#pragma unroll
            for (int e = 0; e < 4; e++) acc[mi][ni][e] = 0.0f;

    for (int kc = 0; kc < 32; kc++) {
        __syncthreads();
#pragma unroll
        for (int i = 0; i < 4; i++) {
            As[tid * ASTH + permU(4 * i + 0)] = ra[i].x;
            As[tid * ASTH + permU(4 * i + 1)] = ra[i].y;
            As[tid * ASTH + permU(4 * i + 2)] = ra[i].z;
            As[tid * ASTH + permU(4 * i + 3)] = ra[i].w;
        }
#pragma unroll
        for (int i = 0; i < 8; i++) {
            Ws[tid * ASTH + permU(2 * i)]     = h2(rw[i].x, rw[i].y);
            Ws[tid * ASTH + permU(2 * i + 1)] = h2(rw[i].z, rw[i].w);
        }
        __syncthreads();
        if (kc < 31) {
#pragma unroll
            for (int i = 0; i < 4; i++)
                ra[i] = *(const uint4*)(Ap + (kc + 1) * 32 + i * 8);
#pragma unroll
            for (int i = 0; i < 8; i++)
                rw[i] = *(const float4*)(Wp + (kc + 1) * 32 + i * 4);
        }
#pragma unroll
        for (int ks = 0; ks < 2; ks++) {
            uint32_t af[4][4];
#pragma unroll
            for (int mi = 0; mi < 4; mi++) {
                int r = wm * 64 + mi * 16 + qr;
                uint2 lo = *(const uint2*)&As[r * ASTH + ks * 8 + qc];
                uint2 hi = *(const uint2*)&As[(r + 8) * ASTH + ks * 8 + qc];
                af[mi][0] = lo.x; af[mi][1] = hi.x;
                af[mi][2] = lo.y; af[mi][3] = hi.y;
            }
#pragma unroll
            for (int ni = 0; ni < 8; ni++) {
                uint2 bb = *(const uint2*)&Ws[(wn * 64 + ni * 8 + qr) * ASTH + ks * 8 + qc];
#pragma unroll
                for (int mi = 0; mi < 4; mi++)
                    mma16(acc[mi][ni], af[mi][0], af[mi][1], af[mi][2], af[mi][3],
                          bb.x, bb.y);
            }
        }
    }

#pragma unroll
    for (int mi = 0; mi < 4; mi++) {
        int rl = m0 + wm * 64 + mi * 16 + qr;
#pragma unroll
        for (int ni = 0; ni < 8; ni++) {
            int cc = n0 + wn * 64 + ni * 8 + qc;
            float2 bv = *(const float2*)&bias[cc];
            *(float2*)&C[(size_t)rl * EE + cc] =
                make_float2(acc[mi][ni][0] + bv.x, acc[mi][ni][1] + bv.y);
            *(float2*)&C[(size_t)(rl + 8) * EE + cc] =
                make_float2(acc[mi][ni][2] + bv.x, acc[mi][ni][3] + bv.y);
        }
    }
}

// ============ Attention (f16 mma + ldmatrix, m=0, register-resident P) ============
// CTA: 128 q-rows, 256 threads (8 warps): wq = w>>1, wk = w&1.
// Smem: plain row-major f16 tiles, stride QP=72 halves (conflict-free ldmatrix).
#define QP 72
#define ATT_DYN (3 * 128 * QP * 2 + 1024)

__global__ __launch_bounds__(256, 1) void attn_tc(
    const int* __restrict__ mask, float* __restrict__ attn_out)
{
    extern __shared__ char smc[];
    __half* Qs = (__half*)smc;                    // [128][QP]
    __half* Ks = Qs + 128 * QP;                   // [128][QP]
    __half* Vs = Ks + 128 * QP;                   // [128 k][QP d]
    float* lred = (float*)(smc + 3 * 128 * QP * 2);  // [2][128]
    float* Osm = (float*)smc;                     // epilogue reuse, stride 68

    const uint32_t sb = smem_u32p(smc);
    const uint32_t qs_b = sb;
    const uint32_t ks_b = sb + 128 * QP * 2;
    const uint32_t vs_b = sb + 2 * 128 * QP * 2;

    const int tid = threadIdx.x;
    const int lane = tid & 31;
    const int w = tid >> 5;
    const int qr = lane >> 2;
    const int qc = 2 * (lane & 3);
    const int wq = w >> 1;
    const int wk = w & 1;
    const int qb = wq * 32;
    const int l7 = lane & 7;
    const int bit3 = ((lane >> 3) & 1) * 8;
    const int bit4 = ((lane >> 4) & 1) * 8;

    const int q0 = blockIdx.x * 128;
    const int h = blockIdx.y;
    const int b = blockIdx.z;

    // copy-thread coords
    const int cr = tid >> 1;
    const int cc32 = (tid & 1) * 32;

    // ---- load Q tile [128 x 64] (straight copy) ----
    {
        const __half* Qg = g_Q + (size_t)(b * LQn + q0 + cr) * EE + h * DD + cc32;
        uint4* dst = (uint4*)&Qs[cr * QP + cc32];
        const uint4* src = (const uint4*)Qg;
#pragma unroll
        for (int i = 0; i < 4; i++) dst[i] = src[i];
    }

    const __half* Kg0 = g_K + (size_t)(b * LKn + cr) * EE + h * DD + cc32;
    const __half* Vg0 = g_V + (size_t)(b * LKn + cr) * EE + h * DD + cc32;

    float oacc[2][8][4];
#pragma unroll
    for (int mi = 0; mi < 2; mi++)
#pragma unroll
        for (int ni = 0; ni < 8; ni++)
#pragma unroll
            for (int e = 0; e < 4; e++) oacc[mi][ni][e] = 0.0f;

    float lacc[2][2] = {{0.0f, 0.0f}, {0.0f, 0.0f}};

    const int* mptr[2][2];
    float* optr[2][2];
#pragma unroll
    for (int mi = 0; mi < 2; mi++)
#pragma unroll
        for (int hi = 0; hi < 2; hi++) {
            int q = q0 + qb + mi * 16 + hi * 8 + qr;
            mptr[mi][hi] = mask + ((size_t)b * LQn + q) * LKn + wk * 64;
            optr[mi][hi] = attn_out + ((size_t)(b * HH + h) * LQn + q) * LKn + wk * 64;
        }

    for (int c = 0; c < 16; c++) {
        __syncthreads();
        {
            const uint4* ks_src = (const uint4*)(Kg0 + (size_t)c * 128 * EE);
            const uint4* vs_src = (const uint4*)(Vg0 + (size_t)c * 128 * EE);
            uint4* kd = (uint4*)&Ks[cr * QP + cc32];
            uint4* vd = (uint4*)&Vs[cr * QP + cc32];
#pragma unroll
            for (int i = 0; i < 4; i++) { kd[i] = ks_src[i]; vd[i] = vs_src[i]; }
        }
        __syncthreads();

        // ---- S = Q @ K^T : warp tile 32q x 64k, 4 ksteps of 16 ----
        float sacc[2][8][4];
#pragma unroll
        for (int mi = 0; mi < 2; mi++)
#pragma unroll
            for (int ni = 0; ni < 8; ni++)
#pragma unroll
                for (int e = 0; e < 4; e++) sacc[mi][ni][e] = 0.0f;

#pragma unroll
        for (int ks = 0; ks < 4; ks++) {
            uint32_t af[2][4];
#pragma unroll
            for (int mi = 0; mi < 2; mi++) {
                uint32_t a = qs_b + ((qb + mi * 16 + bit3 + l7) * QP + ks * 16 + bit4) * 2;
                LDM4(af[mi][0], af[mi][1], af[mi][2], af[mi][3], a);
            }
#pragma unroll
            for (int nii = 0; nii < 4; nii++) {
                uint32_t b0, b1, b2, b3;
                uint32_t a = ks_b + ((wk * 64 + nii * 16 + bit4 + l7) * QP + ks * 16 + bit3) * 2;
                LDM4(b0, b1, b2, b3, a);
                mma16(sacc[0][2 * nii],     af[0][0], af[0][1], af[0][2], af[0][3], b0, b1);
                mma16(sacc[1][2 * nii],     af[1][0], af[1][1], af[1][2], af[1][3], b0, b1);
                mma16(sacc[0][2 * nii + 1], af[0][0], af[0][1], af[0][2], af[0][3], b2, b3);
                mma16(sacc[1][2 * nii + 1], af[1][0], af[1][1], af[1][2], af[1][3], b2, b3);
            }
        }

        // ---- softmax (m=0): mask, p=exp, store p to gmem; p stays in regs ----
#pragma unroll
        for (int mi = 0; mi < 2; mi++) {
#pragma unroll
            for (int ni = 0; ni < 8; ni++) {
                int cb = ni * 8 + qc;
                int2 m2lo = *(const int2*)(mptr[mi][0] + c * 128 + cb);
                int2 m2hi = *(const int2*)(mptr[mi][1] + c * 128 + cb);
                float s0 = sacc[mi][ni][0] * 0.125f; if (m2lo.x == 0) s0 = -1.0e30f;
                float s1 = sacc[mi][ni][1] * 0.125f; if (m2lo.y == 0) s1 = -1.0e30f;
                float s2 = sacc[mi][ni][2] * 0.125f; if (m2hi.x == 0) s2 = -1.0e30f;
                float s3 = sacc[mi][ni][3] * 0.125f; if (m2hi.y == 0) s3 = -1.0e30f;
                float p0 = __expf(s0), p1 = __expf(s1);
                float p2 = __expf(s2), p3 = __expf(s3);
                *(float2*)(optr[mi][0] + c * 128 + cb) = make_float2(p0, p1);
                *(float2*)(optr[mi][1] + c * 128 + cb) = make_float2(p2, p3);
                lacc[mi][0] += p0 + p1;
                lacc[mi][1] += p2 + p3;
                sacc[mi][ni][0] = p0; sacc[mi][ni][1] = p1;
                sacc[mi][ni][2] = p2; sacc[mi][ni][3] = p3;
            }
        }

        // ---- O += P @ V : A-frags from S C-frags, B via ldmatrix.trans ----
#pragma unroll
        for (int j = 0; j < 4; j++) {
            uint32_t a0[2], a1[2], a2[2], a3[2];
#pragma unroll
            for (int mi = 0; mi < 2; mi++) {
                a0[mi] = h2(sacc[mi][2 * j][0], sacc[mi][2 * j][1]);
                a1[mi] = h2(sacc[mi][2 * j][2], sacc[mi][2 * j][3]);
                a2[mi] = h2(sacc[mi][2 * j + 1][0], sacc[mi][2 * j + 1][1]);
                a3[mi] = h2(sacc[mi][2 * j + 1][2], sacc[mi][2 * j + 1][3]);
            }
#pragma unroll
            for (int nii = 0; nii < 4; nii++) {
                uint32_t b0, b1, b2, b3;
                uint32_t a = vs_b + ((wk * 64 + j * 16 + bit3 + l7) * QP + nii * 16 + bit4) * 2;
                LDM4T(b0, b1, b2, b3, a);
                mma16(oacc[0][2 * nii],     a0[0], a1[0], a2[0], a3[0], b0, b1);
                mma16(oacc[1][2 * nii],     a0[1], a1[1], a2[1], a3[1], b0, b1);
                mma16(oacc[0][2 * nii + 1], a0[0], a1[0], a2[0], a3[0], b2, b3);
                mma16(oacc[1][2 * nii + 1], a0[1], a1[1], a2[1], a3[1], b2, b3);
            }
        }
    }

    // ---- epilogue: reduce l (quad + wk) and O (across wk) ----
#pragma unroll
    for (int mi = 0; mi < 2; mi++)
#pragma unroll
        for (int hi = 0; hi < 2; hi++) {
            float v = lacc[mi][hi];
            v += __shfl_xor_sync(0xFFFFFFFF, v, 1);
            v += __shfl_xor_sync(0xFFFFFFFF, v, 2);
            if ((lane & 3) == 0)
                lred[wk * 128 + qb + mi * 16 + hi * 8 + qr] = v;
        }
    __syncthreads();

    if (wk == 1) {
#pragma unroll
        for (int mi = 0; mi < 2; mi++) {
            int row = qb + mi * 16 + qr;
#pragma unroll
            for (int ni = 0; ni < 8; ni++) {
                *(float2*)&Osm[row * 68 + ni * 8 + qc] =
                    make_float2(oacc[mi][ni][0], oacc[mi][ni][1]);
                *(float2*)&Osm[(row + 8) * 68 + ni * 8 + qc] =
                    make_float2(oacc[mi][ni][2], oacc[mi][ni][3]);
            }
        }
    }
    __syncthreads();

    if (wk == 0) {
#pragma unroll
        for (int mi = 0; mi < 2; mi++) {
#pragma unroll
            for (int hi = 0; hi < 2; hi++) {
                int rrow = qb + mi * 16 + hi * 8 + qr;
                float l = lred[rrow] + lred[128 + rrow];
                float inv = 1.0f / l;
                __half* og = g_ctx + (size_t)(b * LQn + q0 + rrow) * EE + h * DD;
#pragma unroll
                for (int ni = 0; ni < 8; ni++) {
                    float2 part = *(const float2*)&Osm[rrow * 68 + ni * 8 + qc];
                    *(uint32_t*)&og[ni * 8 + qc] = h2(
                        (oacc[mi][ni][hi * 2 + 0] + part.x) * inv,
                        (oacc[mi][ni][hi * 2 + 1] + part.y) * inv);
                }
                if ((lane & 3) == 0)
                    g_stats[(size_t)(b * HH + h) * LQn + q0 + rrow] = l;
            }
        }
    }
}

// ---------------- normalize: attn = p / l ----------------
__global__ __launch_bounds__(256) void attn_norm(float* __restrict__ attn)
{
    size_t i4 = (size_t)blockIdx.x * blockDim.x + threadIdx.x;
    const size_t total4 = (size_t)BB * HH * LQn * LKn / 4;
    if (i4 >= total4) return;
    size_t row = (i4 * 4) >> 11;
    float invl = 1.0f / g_stats[row];
    float4 s = ((float4*)attn)[i4];
    s.x *= invl; s.y *= invl; s.z *= invl; s.w *= invl;
    ((float4*)attn)[i4] = s;
}

// ---------------- launch ----------------
extern "C" void kernel_launch(void* const* d_in, const int* in_sizes, int n_in,
                              void* d_out, int out_size)
{
    const float* q_in = (const float*)d_in[0];
    const float* k_in = (const float*)d_in[1];
    const float* v_in = (const float*)d_in[2];
    const int*   mask = (const int*)d_in[3];
    const float* Wq = (const float*)d_in[4];
    const float* bq = (const float*)d_in[5];
    const float* Wk = (const float*)d_in[6];
    const float* bk = (const float*)d_in[7];
    const float* Wv = (const float*)d_in[8];
    const float* bv = (const float*)d_in[9];
    const float* Wo = (const float*)d_in[10];
    const float* bo = (const float*)d_in[11];

    float* out = (float*)d_out;

    __half *gQ, *gK, *gV, *gctx;
    float *gSraw;
    cudaGetSymbolAddress((void**)&gQ, g_Q);
    cudaGetSymbolAddress((void**)&gK, g_K);
    cudaGetSymbolAddress((void**)&gV, g_V);
    cudaGetSymbolAddress((void**)&gctx, g_ctx);
    cudaGetSymbolAddress((void**)&gSraw, g_Sraw);

    const size_t OUT_ELEMS = (size_t)BB * LQn * EE;
    const size_t ATT_ELEMS = (size_t)BB * HH * LQn * LKn;
    bool attn_is_output = ((size_t)out_size >= OUT_ELEMS + ATT_ELEMS);
    float* attnp = attn_is_output ? (out + OUT_ELEMS) : gSraw;

    cudaFuncSetAttribute(attn_tc, cudaFuncAttributeMaxDynamicSharedMemorySize, ATT_DYN);

    dim3 gemmGrid(8, 32);
    gemm_f<<<gemmGrid, 128>>>(q_in, Wq, bq, gQ);
    gemm_f<<<gemmGrid, 128>>>(k_in, Wk, bk, gK);
    gemm_f<<<gemmGrid, 128>>>(v_in, Wv, bv, gV);

    dim3 attnGrid(LQn / 128, HH, BB);  // (16, 16, 2)
    attn_tc<<<attnGrid, 256, ATT_DYN>>>(mask, attnp);

    gemm_out<<<gemmGrid, 128>>>(gctx, Wo, bo, out);

    if (attn_is_output) {
        size_t total4 = ATT_ELEMS / 4;
        int blocks = (int)((total4 + 255) / 256);
        attn_norm<<<blocks, 256>>>(attnp);
    }
}

// round 10
// speedup vs baseline: 1.6344x; 1.0363x over previous
#include <cuda_runtime.h>
#include <cuda_fp16.h>
#include <math.h>
#include <stdint.h>

#define BB 2
#define LQn 2048
#define LKn 2048
#define EE 1024
#define HH 16
#define DD 64

// ---------------- scratch (f16 activations) ----------------
__device__ __half g_Q[(size_t)BB * LQn * EE];
__device__ __half g_K[(size_t)BB * LKn * EE];
__device__ __half g_V[(size_t)BB * LKn * EE];
__device__ __half g_ctx[(size_t)BB * LQn * EE];
__device__ float g_stats[(size_t)BB * HH * LQn];
__device__ float g_Sraw[(size_t)BB * HH * LQn * LKn];

// ---------------- helpers ----------------
__device__ __forceinline__ uint32_t h2(float x, float y) {
    __half2 h = __floats2half2_rn(x, y);
    return *(uint32_t*)&h;
}
__device__ __forceinline__ void mma16(float* d, uint32_t a0, uint32_t a1,
                                      uint32_t a2, uint32_t a3,
                                      uint32_t b0, uint32_t b1) {
    asm volatile(
        "mma.sync.aligned.m16n8k16.row.col.f32.f16.f16.f32 "
        "{%0,%1,%2,%3},{%4,%5,%6,%7},{%8,%9},{%0,%1,%2,%3};"
        : "+f"(d[0]), "+f"(d[1]), "+f"(d[2]), "+f"(d[3])
        : "r"(a0), "r"(a1), "r"(a2), "r"(a3), "r"(b0), "r"(b1));
}
__device__ __forceinline__ int permu(int x) {
    return ((x & 3) << 1) | ((x >> 2) & 1);
}
__device__ __forceinline__ int permU(int U) {
    return (U & ~7) | permu(U & 7);
}
__device__ __forceinline__ uint32_t smem_u32p(const void* p) {
    uint32_t a;
    asm("{ .reg .u64 t; cvta.to.shared.u64 t, %1; cvt.u32.u64 %0, t; }"
        : "=r"(a) : "l"(p));
    return a;
}
#define LDM4(d0, d1, d2, d3, a)                                            \
    asm volatile("ldmatrix.sync.aligned.m8n8.x4.shared.b16 {%0,%1,%2,%3}, [%4];" \
                 : "=r"(d0), "=r"(d1), "=r"(d2), "=r"(d3) : "r"(a))
#define LDM4T(d0, d1, d2, d3, a)                                           \
    asm volatile("ldmatrix.sync.aligned.m8n8.x4.trans.shared.b16 {%0,%1,%2,%3}, [%4];" \
                 : "=r"(d0), "=r"(d1), "=r"(d2), "=r"(d3) : "r"(a))
#define CP16(dst, src)                                                     \
    asm volatile("cp.async.cg.shared.global [%0], [%1], 16;"               \
                 :: "r"(dst), "l"(src))
#define CP_COMMIT() asm volatile("cp.async.commit_group;" ::: "memory")
#define CP_WAIT0()  asm volatile("cp.async.wait_group 0;" ::: "memory")

// ============ GEMM (f32 in, f16 out): C = A @ W^T + bias ============
#define ASTH 18
__global__ __launch_bounds__(128, 2) void gemm_f(
    const float* __restrict__ A, const float* __restrict__ W,
    const float* __restrict__ bias, __half* __restrict__ C)
{
    __shared__ uint32_t As[2][128 * ASTH];
    __shared__ uint32_t Ws[2][128 * ASTH];

    const int tid = threadIdx.x;
    const int lane = tid & 31;
    const int w = tid >> 5;
    const int wm = w >> 1, wn = w & 1;
    const int m0 = blockIdx.y * 128;
    const int n0 = blockIdx.x * 128;
    const int qr = lane >> 2;
    const int qc = 2 * (lane & 3);

    const float* Ap = A + (size_t)(m0 + tid) * EE;
    const float* Wp = W + (size_t)(n0 + tid) * EE;

    float4 ra[8], rw[8];
#pragma unroll
    for (int i = 0; i < 8; i++) {
        ra[i] = *(const float4*)(Ap + i * 4);
        rw[i] = *(const float4*)(Wp + i * 4);
    }

    float acc[4][8][4];
#pragma unroll
    for (int mi = 0; mi < 4; mi++)
#pragma unroll
        for (int ni = 0; ni < 8; ni++)
#pragma unroll
            for (int e = 0; e < 4; e++) acc[mi][ni][e] = 0.0f;

    // store chunk 0 to buf 0
#pragma unroll
    for (int i = 0; i < 8; i++) {
        As[0][tid * ASTH + permU(2 * i)]     = h2(ra[i].x, ra[i].y);
        As[0][tid * ASTH + permU(2 * i + 1)] = h2(ra[i].z, ra[i].w);
        Ws[0][tid * ASTH + permU(2 * i)]     = h2(rw[i].x, rw[i].y);
        Ws[0][tid * ASTH + permU(2 * i + 1)] = h2(rw[i].z, rw[i].w);
    }
    __syncthreads();

    for (int kc = 0; kc < 32; kc++) {
        const int buf = kc & 1;
        if (kc < 31) {
#pragma unroll
            for (int i = 0; i < 8; i++) {
                ra[i] = *(const float4*)(Ap + (kc + 1) * 32 + i * 4);
                rw[i] = *(const float4*)(Wp + (kc + 1) * 32 + i * 4);
            }
        }
#pragma unroll
        for (int ks = 0; ks < 2; ks++) {
            uint32_t af[4][4];
#pragma unroll
            for (int mi = 0; mi < 4; mi++) {
                int r = wm * 64 + mi * 16 + qr;
                uint2 lo = *(const uint2*)&As[buf][r * ASTH + ks * 8 + qc];
                uint2 hi = *(const uint2*)&As[buf][(r + 8) * ASTH + ks * 8 + qc];
                af[mi][0] = lo.x; af[mi][1] = hi.x;
                af[mi][2] = lo.y; af[mi][3] = hi.y;
            }
#pragma unroll
            for (int ni = 0; ni < 8; ni++) {
                uint2 bb = *(const uint2*)&Ws[buf][(wn * 64 + ni * 8 + qr) * ASTH + ks * 8 + qc];
#pragma unroll
                for (int mi = 0; mi < 4; mi++)
                    mma16(acc[mi][ni], af[mi][0], af[mi][1], af[mi][2], af[mi][3],
                          bb.x, bb.y);
            }
        }
        if (kc < 31) {
#pragma unroll
            for (int i = 0; i < 8; i++) {
                As[buf ^ 1][tid * ASTH + permU(2 * i)]     = h2(ra[i].x, ra[i].y);
                As[buf ^ 1][tid * ASTH + permU(2 * i + 1)] = h2(ra[i].z, ra[i].w);
                Ws[buf ^ 1][tid * ASTH + permU(2 * i)]     = h2(rw[i].x, rw[i].y);
                Ws[buf ^ 1][tid * ASTH + permU(2 * i + 1)] = h2(rw[i].z, rw[i].w);
            }
        }
        __syncthreads();
    }

#pragma unroll
    for (int mi = 0; mi < 4; mi++) {
        int rl = m0 + wm * 64 + mi * 16 + qr;
#pragma unroll
        for (int ni = 0; ni < 8; ni++) {
            int cc = n0 + wn * 64 + ni * 8 + qc;
            float2 bv = *(const float2*)&bias[cc];
            *(uint32_t*)&C[(size_t)rl * EE + cc] =
                h2(acc[mi][ni][0] + bv.x, acc[mi][ni][1] + bv.y);
            *(uint32_t*)&C[(size_t)(rl + 8) * EE + cc] =
                h2(acc[mi][ni][2] + bv.x, acc[mi][ni][3] + bv.y);
        }
    }
}

// ============ GEMM (f16 in, f32 out): out = ctx @ Wo^T + bo ============
__global__ __launch_bounds__(128, 2) void gemm_out(
    const __half* __restrict__ A, const float* __restrict__ W,
    const float* __restrict__ bias, float* __restrict__ C)
{
    __shared__ uint32_t As[2][128 * ASTH];
    __shared__ uint32_t Ws[2][128 * ASTH];

    const int tid = threadIdx.x;
    const int lane = tid & 31;
    const int w = tid >> 5;
    const int wm = w >> 1, wn = w & 1;
    const int m0 = blockIdx.y * 128;
    const int n0 = blockIdx.x * 128;
    const int qr = lane >> 2;
    const int qc = 2 * (lane & 3);

    const __half* Ap = A + (size_t)(m0 + tid) * EE;
    const float* Wp = W + (size_t)(n0 + tid) * EE;

    uint4 ra[4];
    float4 rw[8];
#pragma unroll
    for (int i = 0; i < 4; i++) ra[i] = *(const uint4*)(Ap + i * 8);
#pragma unroll
    for (int i = 0; i < 8; i++) rw[i] = *(const float4*)(Wp + i * 4);

    float acc[4][8][4];
#pragma unroll
    for (int mi = 0; mi < 4; mi++)
#pragma unroll
        for (int ni = 0; ni < 8; ni++)
#pragma unroll
            for (int e = 0; e < 4; e++) acc[mi][ni][e] = 0.0f;

#pragma unroll
    for (int i = 0; i < 4; i++) {
        As[0][tid * ASTH + permU(4 * i + 0)] = ra[i].x;
        As[0][tid * ASTH + permU(4 * i + 1)] = ra[i].y;
        As[0][tid * ASTH + permU(4 * i + 2)] = ra[i].z;
        As[0][tid * ASTH + permU(4 * i + 3)] = ra[i].w;
    }
#pragma unroll
    for (int i = 0; i < 8; i++) {
        Ws[0][tid * ASTH + permU(2 * i)]     = h2(rw[i].x, rw[i].y);
        Ws[0][tid * ASTH + permU(2 * i + 1)] = h2(rw[i].z, rw[i].w);
    }
    __syncthreads();

    for (int kc = 0; kc < 32; kc++) {
        const int buf = kc & 1;
        if (kc < 31) {
#pragma unroll
            for (int i = 0; i < 4; i++)
                ra[i] = *(const uint4*)(Ap + (kc + 1) * 32 + i * 8);
#pragma unroll
            for (int i = 0; i < 8; i++)
                rw[i] = *(const float4*)(Wp + (kc + 1) * 32 + i * 4);
        }
#pragma unroll
        for (int ks = 0; ks < 2; ks++) {
            uint32_t af[4][4];
#pragma unroll
            for (int mi = 0; mi < 4; mi++) {
                int r = wm * 64 + mi * 16 + qr;
                uint2 lo = *(const uint2*)&As[buf][r * ASTH + ks * 8 + qc];
                uint2 hi = *(const uint2*)&As[buf][(r + 8) * ASTH + ks * 8 + qc];
                af[mi][0] = lo.x; af[mi][1] = hi.x;
                af[mi][2] = lo.y; af[mi][3] = hi.y;
            }
#pragma unroll
            for (int ni = 0; ni < 8; ni++) {
                uint2 bb = *(const uint2*)&Ws[buf][(wn * 64 + ni * 8 + qr) * ASTH + ks * 8 + qc];
#pragma unroll
                for (int mi = 0; mi < 4; mi++)
                    mma16(acc[mi][ni], af[mi][0], af[mi][1], af[mi][2], af[mi][3],
                          bb.x, bb.y);
            }
        }
        if (kc < 31) {
#pragma unroll
            for (int i = 0; i < 4; i++) {
                As[buf ^ 1][tid * ASTH + permU(4 * i + 0)] = ra[i].x;
                As[buf ^ 1][tid * ASTH + permU(4 * i + 1)] = ra[i].y;
                As[buf ^ 1][tid * ASTH + permU(4 * i + 2)] = ra[i].z;
                As[buf ^ 1][tid * ASTH + permU(4 * i + 3)] = ra[i].w;
            }
#pragma unroll
            for (int i = 0; i < 8; i++) {
                Ws[buf ^ 1][tid * ASTH + permU(2 * i)]     = h2(rw[i].x, rw[i].y);
                Ws[buf ^ 1][tid * ASTH + permU(2 * i + 1)] = h2(rw[i].z, rw[i].w);
            }
        }
        __syncthreads();
    }

#pragma unroll
    for (int mi = 0; mi < 4; mi++) {
        int rl = m0 + wm * 64 + mi * 16 + qr;
#pragma unroll
        for (int ni = 0; ni < 8; ni++) {
            int cc = n0 + wn * 64 + ni * 8 + qc;
            float2 bv = *(const float2*)&bias[cc];
            *(float2*)&C[(size_t)rl * EE + cc] =
                make_float2(acc[mi][ni][0] + bv.x, acc[mi][ni][1] + bv.y);
            *(float2*)&C[(size_t)(rl + 8) * EE + cc] =
                make_float2(acc[mi][ni][2] + bv.x, acc[mi][ni][3] + bv.y);
        }
    }
}

// ============ Attention (f16 mma + ldmatrix + cp.async pipeline) ============
// CTA: 128 q-rows, 256 threads (8 warps): wq = w>>1, wk = w&1.
// Smem: Q + double-buffered K/V, row-major f16, stride QP=72 halves.
#define QP 72
#define TILE_B (128 * QP * 2)
#define ATT_DYN (5 * TILE_B + 1024)

__global__ __launch_bounds__(256, 1) void attn_tc(
    const int* __restrict__ mask, float* __restrict__ attn_out)
{
    extern __shared__ char smc[];
    float* lred = (float*)(smc + 5 * TILE_B);     // [2][128]
    float* Osm = (float*)smc;                     // epilogue reuse, stride 68

    const uint32_t sb = smem_u32p(smc);
    const uint32_t qs_b = sb;
    const uint32_t ks_b[2] = {sb + TILE_B, sb + 2 * TILE_B};
    const uint32_t vs_b[2] = {sb + 3 * TILE_B, sb + 4 * TILE_B};

    const int tid = threadIdx.x;
    const int lane = tid & 31;
    const int w = tid >> 5;
    const int qr = lane >> 2;
    const int qc = 2 * (lane & 3);
    const int wq = w >> 1;
    const int wk = w & 1;
    const int qb = wq * 32;
    const int l7 = lane & 7;
    const int bit3 = ((lane >> 3) & 1) * 8;
    const int bit4 = ((lane >> 4) & 1) * 8;

    const int q0 = blockIdx.x * 128;
    const int h = blockIdx.y;
    const int b = blockIdx.z;

    // copy-thread coords
    const int cr = tid >> 1;
    const int cc32 = (tid & 1) * 32;
    const uint32_t cpdst = (uint32_t)((cr * QP + cc32) * 2);  // byte offset in tile

    const __half* Kg0 = g_K + (size_t)(b * LKn + cr) * EE + h * DD + cc32;
    const __half* Vg0 = g_V + (size_t)(b * LKn + cr) * EE + h * DD + cc32;

    // ---- issue chunk 0 K/V cp.async, then load Q tile ----
    {
        const __half* ks = Kg0;
        const __half* vs = Vg0;
#pragma unroll
        for (int i = 0; i < 4; i++) {
            CP16(ks_b[0] + cpdst + i * 16, (const char*)ks + i * 16);
            CP16(vs_b[0] + cpdst + i * 16, (const char*)vs + i * 16);
        }
        CP_COMMIT();
    }
    {
        __half* Qs = (__half*)smc;
        const __half* Qg = g_Q + (size_t)(b * LQn + q0 + cr) * EE + h * DD + cc32;
        uint4* dst = (uint4*)&Qs[cr * QP + cc32];
        const uint4* src = (const uint4*)Qg;
#pragma unroll
        for (int i = 0; i < 4; i++) dst[i] = src[i];
    }

    float oacc[2][8][4];
#pragma unroll
    for (int mi = 0; mi < 2; mi++)
#pragma unroll
        for (int ni = 0; ni < 8; ni++)
#pragma unroll
            for (int e = 0; e < 4; e++) oacc[mi][ni][e] = 0.0f;

    float lacc[2][2] = {{0.0f, 0.0f}, {0.0f, 0.0f}};

    const int* mptr[2][2];
    float* optr[2][2];
#pragma unroll
    for (int mi = 0; mi < 2; mi++)
#pragma unroll
        for (int hi = 0; hi < 2; hi++) {
            int q = q0 + qb + mi * 16 + hi * 8 + qr;
            mptr[mi][hi] = mask + ((size_t)b * LQn + q) * LKn + wk * 64;
            optr[mi][hi] = attn_out + ((size_t)(b * HH + h) * LQn + q) * LKn + wk * 64;
        }

    for (int c = 0; c < 16; c++) {
        const int buf = c & 1;
        CP_WAIT0();
        __syncthreads();
        if (c < 15) {
            const char* ks = (const char*)(Kg0 + (size_t)(c + 1) * 128 * EE);
            const char* vs = (const char*)(Vg0 + (size_t)(c + 1) * 128 * EE);
#pragma unroll
            for (int i = 0; i < 4; i++) {
                CP16(ks_b[buf ^ 1] + cpdst + i * 16, ks + i * 16);
                CP16(vs_b[buf ^ 1] + cpdst + i * 16, vs + i * 16);
            }
            CP_COMMIT();
        }

        // ---- S = Q @ K^T : warp tile 32q x 64k, 4 ksteps of 16 ----
        float sacc[2][8][4];
#pragma unroll
        for (int mi = 0; mi < 2; mi++)
#pragma unroll
            for (int ni = 0; ni < 8; ni++)
#pragma unroll
                for (int e = 0; e < 4; e++) sacc[mi][ni][e] = 0.0f;

#pragma unroll
        for (int ks = 0; ks < 4; ks++) {
            uint32_t af[2][4];
#pragma unroll
            for (int mi = 0; mi < 2; mi++) {
                uint32_t a = qs_b + ((qb + mi * 16 + bit3 + l7) * QP + ks * 16 + bit4) * 2;
                LDM4(af[mi][0], af[mi][1], af[mi][2], af[mi][3], a);
            }
#pragma unroll
            for (int nii = 0; nii < 4; nii++) {
                uint32_t b0, b1, b2, b3;
                uint32_t a = ks_b[buf] + ((wk * 64 + nii * 16 + bit4 + l7) * QP + ks * 16 + bit3) * 2;
                LDM4(b0, b1, b2, b3, a);
                mma16(sacc[0][2 * nii],     af[0][0], af[0][1], af[0][2], af[0][3], b0, b1);
                mma16(sacc[1][2 * nii],     af[1][0], af[1][1], af[1][2], af[1][3], b0, b1);
                mma16(sacc[0][2 * nii + 1], af[0][0], af[0][1], af[0][2], af[0][3], b2, b3);
                mma16(sacc[1][2 * nii + 1], af[1][0], af[1][1], af[1][2], af[1][3], b2, b3);
            }
        }

        // ---- softmax (m=0): mask, p=exp, store p to gmem; p stays in regs ----
#pragma unroll
        for (int mi = 0; mi < 2; mi++) {
#pragma unroll
            for (int ni = 0; ni < 8; ni++) {
                int cb = ni * 8 + qc;
                int2 m2lo = *(const int2*)(mptr[mi][0] + c * 128 + cb);
                int2 m2hi = *(const int2*)(mptr[mi][1] + c * 128 + cb);
                float s0 = sacc[mi][ni][0] * 0.125f; if (m2lo.x == 0) s0 = -1.0e30f;
                float s1 = sacc[mi][ni][1] * 0.125f; if (m2lo.y == 0) s1 = -1.0e30f;
                float s2 = sacc[mi][ni][2] * 0.125f; if (m2hi.x == 0) s2 = -1.0e30f;
                float s3 = sacc[mi][ni][3] * 0.125f; if (m2hi.y == 0) s3 = -1.0e30f;
                float p0 = __expf(s0), p1 = __expf(s1);
                float p2 = __expf(s2), p3 = __expf(s3);
                *(float2*)(optr[mi][0] + c * 128 + cb) = make_float2(p0, p1);
                *(float2*)(optr[mi][1] + c * 128 + cb) = make_float2(p2, p3);
                lacc[mi][0] += p0 + p1;
                lacc[mi][1] += p2 + p3;
                sacc[mi][ni][0] = p0; sacc[mi][ni][1] = p1;
                sacc[mi][ni][2] = p2; sacc[mi][ni][3] = p3;
            }
        }

        // ---- O += P @ V : A-frags from S C-frags, B via ldmatrix.trans ----
#pragma unroll
        for (int j = 0; j < 4; j++) {
            uint32_t a0[2], a1[2], a2[2], a3[2];
#pragma unroll
            for (int mi = 0; mi < 2; mi++) {
                a0[mi] = h2(sacc[mi][2 * j][0], sacc[mi][2 * j][1]);
                a1[mi] = h2(sacc[mi][2 * j][2], sacc[mi][2 * j][3]);
                a2[mi] = h2(sacc[mi][2 * j + 1][0], sacc[mi][2 * j + 1][1]);
                a3[mi] = h2(sacc[mi][2 * j + 1][2], sacc[mi][2 * j + 1][3]);
            }
#pragma unroll
            for (int nii = 0; nii < 4; nii++) {
                uint32_t b0, b1, b2, b3;
                uint32_t a = vs_b[buf] + ((wk * 64 + j * 16 + bit3 + l7) * QP + nii * 16 + bit4) * 2;
                LDM4T(b0, b1, b2, b3, a);
                mma16(oacc[0][2 * nii],     a0[0], a1[0], a2[0], a3[0], b0, b1);
                mma16(oacc[1][2 * nii],     a0[1], a1[1], a2[1], a3[1], b0, b1);
                mma16(oacc[0][2 * nii + 1], a0[0], a1[0], a2[0], a3[0], b2, b3);
                mma16(oacc[1][2 * nii + 1], a0[1], a1[1], a2[1], a3[1], b2, b3);
            }
        }
    }

    // ---- epilogue: reduce l (quad + wk) and O (across wk) ----
#pragma unroll
    for (int mi = 0; mi < 2; mi++)
#pragma unroll
        for (int hi = 0; hi < 2; hi++) {
            float v = lacc[mi][hi];
            v += __shfl_xor_sync(0xFFFFFFFF, v, 1);
            v += __shfl_xor_sync(0xFFFFFFFF, v, 2);
            if ((lane & 3) == 0)
                lred[wk * 128 + qb + mi * 16 + hi * 8 + qr] = v;
        }
    __syncthreads();

    if (wk == 1) {
#pragma unroll
        for (int mi = 0; mi < 2; mi++) {
            int row = qb + mi * 16 + qr;
#pragma unroll
            for (int ni = 0; ni < 8; ni++) {
                *(float2*)&Osm[row * 68 + ni * 8 + qc] =
                    make_float2(oacc[mi][ni][0], oacc[mi][ni][1]);
                *(float2*)&Osm[(row + 8) * 68 + ni * 8 + qc] =
                    make_float2(oacc[mi][ni][2], oacc[mi][ni][3]);
            }
        }
    }
    __syncthreads();

    if (wk == 0) {
#pragma unroll
        for (int mi = 0; mi < 2; mi++) {
#pragma unroll
            for (int hi = 0; hi < 2; hi++) {
                int rrow = qb + mi * 16 + hi * 8 + qr;
                float l = lred[rrow] + lred[128 + rrow];
                float inv = 1.0f / l;
                __half* og = g_ctx + (size_t)(b * LQn + q0 + rrow) * EE + h * DD;
#pragma unroll
                for (int ni = 0; ni < 8; ni++) {
                    float2 part = *(const float2*)&Osm[rrow * 68 + ni * 8 + qc];
                    *(uint32_t*)&og[ni * 8 + qc] = h2(
                        (oacc[mi][ni][hi * 2 + 0] + part.x) * inv,
                        (oacc[mi][ni][hi * 2 + 1] + part.y) * inv);
                }
                if ((lane & 3) == 0)
                    g_stats[(size_t)(b * HH + h) * LQn + q0 + rrow] = l;
            }
        }
    }
}

// ---------------- normalize: attn = p / l ----------------
__global__ __launch_bounds__(256) void attn_norm(float* __restrict__ attn)
{
    size_t i4 = (size_t)blockIdx.x * blockDim.x + threadIdx.x;
    const size_t total4 = (size_t)BB * HH * LQn * LKn / 4;
    if (i4 >= total4) return;
    size_t row = (i4 * 4) >> 11;
    float invl = 1.0f / g_stats[row];
    float4 s = ((float4*)attn)[i4];
    s.x *= invl; s.y *= invl; s.z *= invl; s.w *= invl;
    ((float4*)attn)[i4] = s;
}

// ---------------- launch ----------------
extern "C" void kernel_launch(void* const* d_in, const int* in_sizes, int n_in,
                              void* d_out, int out_size)
{
    const float* q_in = (const float*)d_in[0];
    const float* k_in = (const float*)d_in[1];
    const float* v_in = (const float*)d_in[2];
    const int*   mask = (const int*)d_in[3];
    const float* Wq = (const float*)d_in[4];
    const float* bq = (const float*)d_in[5];
    const float* Wk = (const float*)d_in[6];
    const float* bk = (const float*)d_in[7];
    const float* Wv = (const float*)d_in[8];
    const float* bv = (const float*)d_in[9];
    const float* Wo = (const float*)d_in[10];
    const float* bo = (const float*)d_in[11];

    float* out = (float*)d_out;

    __half *gQ, *gK, *gV, *gctx;
    float *gSraw;
    cudaGetSymbolAddress((void**)&gQ, g_Q);
    cudaGetSymbolAddress((void**)&gK, g_K);
    cudaGetSymbolAddress((void**)&gV, g_V);
    cudaGetSymbolAddress((void**)&gctx, g_ctx);
    cudaGetSymbolAddress((void**)&gSraw, g_Sraw);

    const size_t OUT_ELEMS = (size_t)BB * LQn * EE;
    const size_t ATT_ELEMS = (size_t)BB * HH * LQn * LKn;
    bool attn_is_output = ((size_t)out_size >= OUT_ELEMS + ATT_ELEMS);
    float* attnp = attn_is_output ? (out + OUT_ELEMS) : gSraw;

    cudaFuncSetAttribute(attn_tc, cudaFuncAttributeMaxDynamicSharedMemorySize, ATT_DYN);

    dim3 gemmGrid(8, 32);
    gemm_f<<<gemmGrid, 128>>>(q_in, Wq, bq, gQ);
    gemm_f<<<gemmGrid, 128>>>(k_in, Wk, bk, gK);
    gemm_f<<<gemmGrid, 128>>>(v_in, Wv, bv, gV);

    dim3 attnGrid(LQn / 128, HH, BB);  // (16, 16, 2)
    attn_tc<<<attnGrid, 256, ATT_DYN>>>(mask, attnp);

    gemm_out<<<gemmGrid, 128>>>(gctx, Wo, bo, out);

    if (attn_is_output) {
        size_t total4 = ATT_ELEMS / 4;
        int blocks = (int)((total4 + 255) / 256);
        attn_norm<<<blocks, 256>>>(attnp);
    }
}

// round 11
// speedup vs baseline: 1.7880x; 1.0940x over previous
#include <cuda_runtime.h>
#include <cuda_fp16.h>
#include <math.h>
#include <stdint.h>

#define BB 2
#define LQn 2048
#define LKn 2048
#define EE 1024
#define HH 16
#define DD 64

// ---------------- scratch (f16 activations) ----------------
__device__ __half g_Q[(size_t)BB * LQn * EE];
__device__ __half g_K[(size_t)BB * LKn * EE];
__device__ __half g_V[(size_t)BB * LKn * EE];
__device__ __half g_ctx[(size_t)BB * LQn * EE];
__device__ __half g_P[(size_t)BB * HH * LQn * LKn];   // unnormalized p (f16)
__device__ float g_stats[(size_t)BB * HH * LQn];
__device__ float g_Sraw[(size_t)BB * HH * LQn * LKn]; // fallback attn output

// ---------------- helpers ----------------
__device__ __forceinline__ uint32_t h2(float x, float y) {
    __half2 h = __floats2half2_rn(x, y);
    return *(uint32_t*)&h;
}
__device__ __forceinline__ void mma16(float* d, uint32_t a0, uint32_t a1,
                                      uint32_t a2, uint32_t a3,
                                      uint32_t b0, uint32_t b1) {
    asm volatile(
        "mma.sync.aligned.m16n8k16.row.col.f32.f16.f16.f32 "
        "{%0,%1,%2,%3},{%4,%5,%6,%7},{%8,%9},{%0,%1,%2,%3};"
        : "+f"(d[0]), "+f"(d[1]), "+f"(d[2]), "+f"(d[3])
        : "r"(a0), "r"(a1), "r"(a2), "r"(a3), "r"(b0), "r"(b1));
}
__device__ __forceinline__ int permu(int x) {
    return ((x & 3) << 1) | ((x >> 2) & 1);
}
__device__ __forceinline__ int permU(int U) {
    return (U & ~7) | permu(U & 7);
}
__device__ __forceinline__ uint32_t smem_u32p(const void* p) {
    uint32_t a;
    asm("{ .reg .u64 t; cvta.to.shared.u64 t, %1; cvt.u32.u64 %0, t; }"
        : "=r"(a) : "l"(p));
    return a;
}
#define LDM4(d0, d1, d2, d3, a)                                            \
    asm volatile("ldmatrix.sync.aligned.m8n8.x4.shared.b16 {%0,%1,%2,%3}, [%4];" \
                 : "=r"(d0), "=r"(d1), "=r"(d2), "=r"(d3) : "r"(a))
#define LDM4T(d0, d1, d2, d3, a)                                           \
    asm volatile("ldmatrix.sync.aligned.m8n8.x4.trans.shared.b16 {%0,%1,%2,%3}, [%4];" \
                 : "=r"(d0), "=r"(d1), "=r"(d2), "=r"(d3) : "r"(a))
#define CP16(dst, src)                                                     \
    asm volatile("cp.async.cg.shared.global [%0], [%1], 16;"               \
                 :: "r"(dst), "l"(src))
#define CP_COMMIT() asm volatile("cp.async.commit_group;" ::: "memory")
#define CP_WAIT0()  asm volatile("cp.async.wait_group 0;" ::: "memory")

// ============ Merged QKV GEMM (f32 in, f16 out): Cz = Az @ Wz^T + biasz ============
#define ASTH 18
__global__ __launch_bounds__(128, 2) void gemm_qkv(
    const float* __restrict__ A0, const float* __restrict__ A1,
    const float* __restrict__ A2,
    const float* __restrict__ W0, const float* __restrict__ W1,
    const float* __restrict__ W2,
    const float* __restrict__ b0p, const float* __restrict__ b1p,
    const float* __restrict__ b2p,
    __half* __restrict__ C0, __half* __restrict__ C1, __half* __restrict__ C2)
{
    __shared__ uint32_t As[2][128 * ASTH];
    __shared__ uint32_t Ws[2][128 * ASTH];

    const int z = blockIdx.z;
    const float* A = (z == 0) ? A0 : (z == 1) ? A1 : A2;
    const float* W = (z == 0) ? W0 : (z == 1) ? W1 : W2;
    const float* bias = (z == 0) ? b0p : (z == 1) ? b1p : b2p;
    __half* C = (z == 0) ? C0 : (z == 1) ? C1 : C2;

    const int tid = threadIdx.x;
    const int lane = tid & 31;
    const int w = tid >> 5;
    const int wm = w >> 1, wn = w & 1;
    const int m0 = blockIdx.y * 128;
    const int n0 = blockIdx.x * 128;
    const int qr = lane >> 2;
    const int qc = 2 * (lane & 3);

    const float* Ap = A + (size_t)(m0 + tid) * EE;
    const float* Wp = W + (size_t)(n0 + tid) * EE;

    float4 ra[8], rw[8];
#pragma unroll
    for (int i = 0; i < 8; i++) {
        ra[i] = *(const float4*)(Ap + i * 4);
        rw[i] = *(const float4*)(Wp + i * 4);
    }

    float acc[4][8][4];
#pragma unroll
    for (int mi = 0; mi < 4; mi++)
#pragma unroll
        for (int ni = 0; ni < 8; ni++)
#pragma unroll
            for (int e = 0; e < 4; e++) acc[mi][ni][e] = 0.0f;

#pragma unroll
    for (int i = 0; i < 8; i++) {
        As[0][tid * ASTH + permU(2 * i)]     = h2(ra[i].x, ra[i].y);
        As[0][tid * ASTH + permU(2 * i + 1)] = h2(ra[i].z, ra[i].w);
        Ws[0][tid * ASTH + permU(2 * i)]     = h2(rw[i].x, rw[i].y);
        Ws[0][tid * ASTH + permU(2 * i + 1)] = h2(rw[i].z, rw[i].w);
    }
    __syncthreads();

    for (int kc = 0; kc < 32; kc++) {
        const int buf = kc & 1;
        if (kc < 31) {
#pragma unroll
            for (int i = 0; i < 8; i++) {
                ra[i] = *(const float4*)(Ap + (kc + 1) * 32 + i * 4);
                rw[i] = *(const float4*)(Wp + (kc + 1) * 32 + i * 4);
            }
        }
#pragma unroll
        for (int ks = 0; ks < 2; ks++) {
            uint32_t af[4][4];
#pragma unroll
            for (int mi = 0; mi < 4; mi++) {
                int r = wm * 64 + mi * 16 + qr;
                uint2 lo = *(const uint2*)&As[buf][r * ASTH + ks * 8 + qc];
                uint2 hi = *(const uint2*)&As[buf][(r + 8) * ASTH + ks * 8 + qc];
                af[mi][0] = lo.x; af[mi][1] = hi.x;
                af[mi][2] = lo.y; af[mi][3] = hi.y;
            }
#pragma unroll
            for (int ni = 0; ni < 8; ni++) {
                uint2 bb = *(const uint2*)&Ws[buf][(wn * 64 + ni * 8 + qr) * ASTH + ks * 8 + qc];
#pragma unroll
                for (int mi = 0; mi < 4; mi++)
                    mma16(acc[mi][ni], af[mi][0], af[mi][1], af[mi][2], af[mi][3],
                          bb.x, bb.y);
            }
        }
        if (kc < 31) {
#pragma unroll
            for (int i = 0; i < 8; i++) {
                As[buf ^ 1][tid * ASTH + permU(2 * i)]     = h2(ra[i].x, ra[i].y);
                As[buf ^ 1][tid * ASTH + permU(2 * i + 1)] = h2(ra[i].z, ra[i].w);
                Ws[buf ^ 1][tid * ASTH + permU(2 * i)]     = h2(rw[i].x, rw[i].y);
                Ws[buf ^ 1][tid * ASTH + permU(2 * i + 1)] = h2(rw[i].z, rw[i].w);
            }
        }
        __syncthreads();
    }

#pragma unroll
    for (int mi = 0; mi < 4; mi++) {
        int rl = m0 + wm * 64 + mi * 16 + qr;
#pragma unroll
        for (int ni = 0; ni < 8; ni++) {
            int cc = n0 + wn * 64 + ni * 8 + qc;
            float2 bv = *(const float2*)&bias[cc];
            *(uint32_t*)&C[(size_t)rl * EE + cc] =
                h2(acc[mi][ni][0] + bv.x, acc[mi][ni][1] + bv.y);
            *(uint32_t*)&C[(size_t)(rl + 8) * EE + cc] =
                h2(acc[mi][ni][2] + bv.x, acc[mi][ni][3] + bv.y);
        }
    }
}

// ============ GEMM (f16 in, f32 out): out = ctx @ Wo^T + bo ============
__global__ __launch_bounds__(128, 2) void gemm_out(
    const __half* __restrict__ A, const float* __restrict__ W,
    const float* __restrict__ bias, float* __restrict__ C)
{
    __shared__ uint32_t As[2][128 * ASTH];
    __shared__ uint32_t Ws[2][128 * ASTH];

    const int tid = threadIdx.x;
    const int lane = tid & 31;
    const int w = tid >> 5;
    const int wm = w >> 1, wn = w & 1;
    const int m0 = blockIdx.y * 128;
    const int n0 = blockIdx.x * 128;
    const int qr = lane >> 2;
    const int qc = 2 * (lane & 3);

    const __half* Ap = A + (size_t)(m0 + tid) * EE;
    const float* Wp = W + (size_t)(n0 + tid) * EE;

    uint4 ra[4];
    float4 rw[8];
#pragma unroll
    for (int i = 0; i < 4; i++) ra[i] = *(const uint4*)(Ap + i * 8);
#pragma unroll
    for (int i = 0; i < 8; i++) rw[i] = *(const float4*)(Wp + i * 4);

    float acc[4][8][4];
#pragma unroll
    for (int mi = 0; mi < 4; mi++)
#pragma unroll
        for (int ni = 0; ni < 8; ni++)
#pragma unroll
            for (int e = 0; e < 4; e++) acc[mi][ni][e] = 0.0f;

#pragma unroll
    for (int i = 0; i < 4; i++) {
        As[0][tid * ASTH + permU(4 * i + 0)] = ra[i].x;
        As[0][tid * ASTH + permU(4 * i + 1)] = ra[i].y;
        As[0][tid * ASTH + permU(4 * i + 2)] = ra[i].z;
        As[0][tid * ASTH + permU(4 * i + 3)] = ra[i].w;
    }
#pragma unroll
    for (int i = 0; i < 8; i++) {
        Ws[0][tid * ASTH + permU(2 * i)]     = h2(rw[i].x, rw[i].y);
        Ws[0][tid * ASTH + permU(2 * i + 1)] = h2(rw[i].z, rw[i].w);
    }
    __syncthreads();

    for (int kc = 0; kc < 32; kc++) {
        const int buf = kc & 1;
        if (kc < 31) {
#pragma unroll
            for (int i = 0; i < 4; i++)
                ra[i] = *(const uint4*)(Ap + (kc + 1) * 32 + i * 8);
#pragma unroll
            for (int i = 0; i < 8; i++)
                rw[i] = *(const float4*)(Wp + (kc + 1) * 32 + i * 4);
        }
#pragma unroll
        for (int ks = 0; ks < 2; ks++) {
            uint32_t af[4][4];
#pragma unroll
            for (int mi = 0; mi < 4; mi++) {
                int r = wm * 64 + mi * 16 + qr;
                uint2 lo = *(const uint2*)&As[buf][r * ASTH + ks * 8 + qc];
                uint2 hi = *(const uint2*)&As[buf][(r + 8) * ASTH + ks * 8 + qc];
                af[mi][0] = lo.x; af[mi][1] = hi.x;
                af[mi][2] = lo.y; af[mi][3] = hi.y;
            }
#pragma unroll
            for (int ni = 0; ni < 8; ni++) {
                uint2 bb = *(const uint2*)&Ws[buf][(wn * 64 + ni * 8 + qr) * ASTH + ks * 8 + qc];
#pragma unroll
                for (int mi = 0; mi < 4; mi++)
                    mma16(acc[mi][ni], af[mi][0], af[mi][1], af[mi][2], af[mi][3],
                          bb.x, bb.y);
            }
        }
        if (kc < 31) {
#pragma unroll
            for (int i = 0; i < 4; i++) {
                As[buf ^ 1][tid * ASTH + permU(4 * i + 0)] = ra[i].x;
                As[buf ^ 1][tid * ASTH + permU(4 * i + 1)] = ra[i].y;
                As[buf ^ 1][tid * ASTH + permU(4 * i + 2)] = ra[i].z;
                As[buf ^ 1][tid * ASTH + permU(4 * i + 3)] = ra[i].w;
            }
#pragma unroll
            for (int i = 0; i < 8; i++) {
                Ws[buf ^ 1][tid * ASTH + permU(2 * i)]     = h2(rw[i].x, rw[i].y);
                Ws[buf ^ 1][tid * ASTH + permU(2 * i + 1)] = h2(rw[i].z, rw[i].w);
            }
        }
        __syncthreads();
    }

#pragma unroll
    for (int mi = 0; mi < 4; mi++) {
        int rl = m0 + wm * 64 + mi * 16 + qr;
#pragma unroll
        for (int ni = 0; ni < 8; ni++) {
            int cc = n0 + wn * 64 + ni * 8 + qc;
            float2 bv = *(const float2*)&bias[cc];
            *(float2*)&C[(size_t)rl * EE + cc] =
                make_float2(acc[mi][ni][0] + bv.x, acc[mi][ni][1] + bv.y);
            *(float2*)&C[(size_t)(rl + 8) * EE + cc] =
                make_float2(acc[mi][ni][2] + bv.x, acc[mi][ni][3] + bv.y);
        }
    }
}

// ============ Attention (f16 mma + ldmatrix + cp.async pipeline, f16 p-store) ============
#define QP 72
#define TILE_B (128 * QP * 2)
#define ATT_DYN (5 * TILE_B + 1024)

__global__ __launch_bounds__(256, 1) void attn_tc(const int* __restrict__ mask)
{
    extern __shared__ char smc[];
    float* lred = (float*)(smc + 5 * TILE_B);     // [2][128]
    float* Osm = (float*)smc;                     // epilogue reuse, stride 68

    const uint32_t sb = smem_u32p(smc);
    const uint32_t qs_b = sb;
    const uint32_t ks_b[2] = {sb + TILE_B, sb + 2 * TILE_B};
    const uint32_t vs_b[2] = {sb + 3 * TILE_B, sb + 4 * TILE_B};

    const int tid = threadIdx.x;
    const int lane = tid & 31;
    const int w = tid >> 5;
    const int qr = lane >> 2;
    const int qc = 2 * (lane & 3);
    const int wq = w >> 1;
    const int wk = w & 1;
    const int qb = wq * 32;
    const int l7 = lane & 7;
    const int bit3 = ((lane >> 3) & 1) * 8;
    const int bit4 = ((lane >> 4) & 1) * 8;

    const int q0 = blockIdx.x * 128;
    const int h = blockIdx.y;
    const int b = blockIdx.z;

    const int cr = tid >> 1;
    const int cc32 = (tid & 1) * 32;
    const uint32_t cpdst = (uint32_t)((cr * QP + cc32) * 2);

    const __half* Kg0 = g_K + (size_t)(b * LKn + cr) * EE + h * DD + cc32;
    const __half* Vg0 = g_V + (size_t)(b * LKn + cr) * EE + h * DD + cc32;

    {
#pragma unroll
        for (int i = 0; i < 4; i++) {
            CP16(ks_b[0] + cpdst + i * 16, (const char*)Kg0 + i * 16);
            CP16(vs_b[0] + cpdst + i * 16, (const char*)Vg0 + i * 16);
        }
        CP_COMMIT();
    }
    {
        __half* Qs = (__half*)smc;
        const __half* Qg = g_Q + (size_t)(b * LQn + q0 + cr) * EE + h * DD + cc32;
        uint4* dst = (uint4*)&Qs[cr * QP + cc32];
        const uint4* src = (const uint4*)Qg;
#pragma unroll
        for (int i = 0; i < 4; i++) dst[i] = src[i];
    }

    float oacc[2][8][4];
#pragma unroll
    for (int mi = 0; mi < 2; mi++)
#pragma unroll
        for (int ni = 0; ni < 8; ni++)
#pragma unroll
            for (int e = 0; e < 4; e++) oacc[mi][ni][e] = 0.0f;

    float lacc[2][2] = {{0.0f, 0.0f}, {0.0f, 0.0f}};

    const int* mptr[2][2];
    __half* pptr[2][2];
#pragma unroll
    for (int mi = 0; mi < 2; mi++)
#pragma unroll
        for (int hi = 0; hi < 2; hi++) {
            int q = q0 + qb + mi * 16 + hi * 8 + qr;
            mptr[mi][hi] = mask + ((size_t)b * LQn + q) * LKn + wk * 64;
            pptr[mi][hi] = g_P + ((size_t)(b * HH + h) * LQn + q) * LKn + wk * 64;
        }

    for (int c = 0; c < 16; c++) {
        const int buf = c & 1;
        CP_WAIT0();
        __syncthreads();
        if (c < 15) {
            const char* ks = (const char*)(Kg0 + (size_t)(c + 1) * 128 * EE);
            const char* vs = (const char*)(Vg0 + (size_t)(c + 1) * 128 * EE);
#pragma unroll
            for (int i = 0; i < 4; i++) {
                CP16(ks_b[buf ^ 1] + cpdst + i * 16, ks + i * 16);
                CP16(vs_b[buf ^ 1] + cpdst + i * 16, vs + i * 16);
            }
            CP_COMMIT();
        }

        // ---- S = Q @ K^T ----
        float sacc[2][8][4];
#pragma unroll
        for (int mi = 0; mi < 2; mi++)
#pragma unroll
            for (int ni = 0; ni < 8; ni++)
#pragma unroll
                for (int e = 0; e < 4; e++) sacc[mi][ni][e] = 0.0f;

#pragma unroll
        for (int ks = 0; ks < 4; ks++) {
            uint32_t af[2][4];
#pragma unroll
            for (int mi = 0; mi < 2; mi++) {
                uint32_t a = qs_b + ((qb + mi * 16 + bit3 + l7) * QP + ks * 16 + bit4) * 2;
                LDM4(af[mi][0], af[mi][1], af[mi][2], af[mi][3], a);
            }
#pragma unroll
            for (int nii = 0; nii < 4; nii++) {
                uint32_t b0, b1, b2, b3;
                uint32_t a = ks_b[buf] + ((wk * 64 + nii * 16 + bit4 + l7) * QP + ks * 16 + bit3) * 2;
                LDM4(b0, b1, b2, b3, a);
                mma16(sacc[0][2 * nii],     af[0][0], af[0][1], af[0][2], af[0][3], b0, b1);
                mma16(sacc[1][2 * nii],     af[1][0], af[1][1], af[1][2], af[1][3], b0, b1);
                mma16(sacc[0][2 * nii + 1], af[0][0], af[0][1], af[0][2], af[0][3], b2, b3);
                mma16(sacc[1][2 * nii + 1], af[1][0], af[1][1], af[1][2], af[1][3], b2, b3);
            }
        }

        // ---- softmax (m=0): mask, p=exp, pack f16, store to g_P; keep for PV ----
#pragma unroll
        for (int mi = 0; mi < 2; mi++) {
#pragma unroll
            for (int ni = 0; ni < 8; ni++) {
                int cb = ni * 8 + qc;
                int2 m2lo = *(const int2*)(mptr[mi][0] + c * 128 + cb);
                int2 m2hi = *(const int2*)(mptr[mi][1] + c * 128 + cb);
                float s0 = sacc[mi][ni][0] * 0.125f; if (m2lo.x == 0) s0 = -1.0e30f;
                float s1 = sacc[mi][ni][1] * 0.125f; if (m2lo.y == 0) s1 = -1.0e30f;
                float s2 = sacc[mi][ni][2] * 0.125f; if (m2hi.x == 0) s2 = -1.0e30f;
                float s3 = sacc[mi][ni][3] * 0.125f; if (m2hi.y == 0) s3 = -1.0e30f;
                float p0 = __expf(s0), p1 = __expf(s1);
                float p2 = __expf(s2), p3 = __expf(s3);
                uint32_t plo = h2(p0, p1);
                uint32_t phi = h2(p2, p3);
                *(uint32_t*)(pptr[mi][0] + c * 128 + cb) = plo;
                *(uint32_t*)(pptr[mi][1] + c * 128 + cb) = phi;
                lacc[mi][0] += p0 + p1;
                lacc[mi][1] += p2 + p3;
                sacc[mi][ni][0] = p0; sacc[mi][ni][1] = p1;
                sacc[mi][ni][2] = p2; sacc[mi][ni][3] = p3;
            }
        }

        // ---- O += P @ V ----
#pragma unroll
        for (int j = 0; j < 4; j++) {
            uint32_t a0[2], a1[2], a2[2], a3[2];
#pragma unroll
            for (int mi = 0; mi < 2; mi++) {
                a0[mi] = h2(sacc[mi][2 * j][0], sacc[mi][2 * j][1]);
                a1[mi] = h2(sacc[mi][2 * j][2], sacc[mi][2 * j][3]);
                a2[mi] = h2(sacc[mi][2 * j + 1][0], sacc[mi][2 * j + 1][1]);
                a3[mi] = h2(sacc[mi][2 * j + 1][2], sacc[mi][2 * j + 1][3]);
            }
#pragma unroll
            for (int nii = 0; nii < 4; nii++) {
                uint32_t b0, b1, b2, b3;
                uint32_t a = vs_b[buf] + ((wk * 64 + j * 16 + bit3 + l7) * QP + nii * 16 + bit4) * 2;
                LDM4T(b0, b1, b2, b3, a);
                mma16(oacc[0][2 * nii],     a0[0], a1[0], a2[0], a3[0], b0, b1);
                mma16(oacc[1][2 * nii],     a0[1], a1[1], a2[1], a3[1], b0, b1);
                mma16(oacc[0][2 * nii + 1], a0[0], a1[0], a2[0], a3[0], b2, b3);
                mma16(oacc[1][2 * nii + 1], a0[1], a1[1], a2[1], a3[1], b2, b3);
            }
        }
    }

    // ---- epilogue ----
#pragma unroll
    for (int mi = 0; mi < 2; mi++)
#pragma unroll
        for (int hi = 0; hi < 2; hi++) {
            float v = lacc[mi][hi];
            v += __shfl_xor_sync(0xFFFFFFFF, v, 1);
            v += __shfl_xor_sync(0xFFFFFFFF, v, 2);
            if ((lane & 3) == 0)
                lred[wk * 128 + qb + mi * 16 + hi * 8 + qr] = v;
        }
    __syncthreads();

    if (wk == 1) {
#pragma unroll
        for (int mi = 0; mi < 2; mi++) {
            int row = qb + mi * 16 + qr;
#pragma unroll
            for (int ni = 0; ni < 8; ni++) {
                *(float2*)&Osm[row * 68 + ni * 8 + qc] =
                    make_float2(oacc[mi][ni][0], oacc[mi][ni][1]);
                *(float2*)&Osm[(row + 8) * 68 + ni * 8 + qc] =
                    make_float2(oacc[mi][ni][2], oacc[mi][ni][3]);
            }
        }
    }
    __syncthreads();

    if (wk == 0) {
#pragma unroll
        for (int mi = 0; mi < 2; mi++) {
#pragma unroll
            for (int hi = 0; hi < 2; hi++) {
                int rrow = qb + mi * 16 + hi * 8 + qr;
                float l = lred[rrow] + lred[128 + rrow];
                float inv = 1.0f / l;
                __half* og = g_ctx + (size_t)(b * LQn + q0 + rrow) * EE + h * DD;
#pragma unroll
                for (int ni = 0; ni < 8; ni++) {
                    float2 part = *(const float2*)&Osm[rrow * 68 + ni * 8 + qc];
                    *(uint32_t*)&og[ni * 8 + qc] = h2(
                        (oacc[mi][ni][hi * 2 + 0] + part.x) * inv,
                        (oacc[mi][ni][hi * 2 + 1] + part.y) * inv);
                }
                if ((lane & 3) == 0)
                    g_stats[(size_t)(b * HH + h) * LQn + q0 + rrow] = l;
            }
        }
    }
}

// ---------------- normalize: attn = h2f(p_f16) / l ----------------
__global__ __launch_bounds__(256) void attn_norm(float* __restrict__ attn)
{
    size_t i4 = (size_t)blockIdx.x * blockDim.x + threadIdx.x;
    const size_t total4 = (size_t)BB * HH * LQn * LKn / 4;
    if (i4 >= total4) return;
    size_t row = (i4 * 4) >> 11;
    float invl = 1.0f / g_stats[row];
    uint2 pv = *(const uint2*)(g_P + i4 * 4);
    __half2 h0 = *(__half2*)&pv.x;
    __half2 h1 = *(__half2*)&pv.y;
    float2 f0 = __half22float2(h0);
    float2 f1 = __half22float2(h1);
    float4 s = make_float4(f0.x * invl, f0.y * invl, f1.x * invl, f1.y * invl);
    ((float4*)attn)[i4] = s;
}

// ---------------- launch ----------------
extern "C" void kernel_launch(void* const* d_in, const int* in_sizes, int n_in,
                              void* d_out, int out_size)
{
    const float* q_in = (const float*)d_in[0];
    const float* k_in = (const float*)d_in[1];
    const float* v_in = (const float*)d_in[2];
    const int*   mask = (const int*)d_in[3];
    const float* Wq = (const float*)d_in[4];
    const float* bq = (const float*)d_in[5];
    const float* Wk = (const float*)d_in[6];
    const float* bk = (const float*)d_in[7];
    const float* Wv = (const float*)d_in[8];
    const float* bv = (const float*)d_in[9];
    const float* Wo = (const float*)d_in[10];
    const float* bo = (const float*)d_in[11];

    float* out = (float*)d_out;

    __half *gQ, *gK, *gV, *gctx;
    float *gSraw;
    cudaGetSymbolAddress((void**)&gQ, g_Q);
    cudaGetSymbolAddress((void**)&gK, g_K);
    cudaGetSymbolAddress((void**)&gV, g_V);
    cudaGetSymbolAddress((void**)&gctx, g_ctx);
    cudaGetSymbolAddress((void**)&gSraw, g_Sraw);

    const size_t OUT_ELEMS = (size_t)BB * LQn * EE;
    const size_t ATT_ELEMS = (size_t)BB * HH * LQn * LKn;
    bool attn_is_output = ((size_t)out_size >= OUT_ELEMS + ATT_ELEMS);
    float* attnp = attn_is_output ? (out + OUT_ELEMS) : gSraw;

    cudaFuncSetAttribute(attn_tc, cudaFuncAttributeMaxDynamicSharedMemorySize, ATT_DYN);

    dim3 qkvGrid(8, 32, 3);
    gemm_qkv<<<qkvGrid, 128>>>(q_in, k_in, v_in, Wq, Wk, Wv, bq, bk, bv,
                               gQ, gK, gV);

    dim3 attnGrid(LQn / 128, HH, BB);  // (16, 16, 2)
    attn_tc<<<attnGrid, 256, ATT_DYN>>>(mask);

    gemm_out<<<dim3(8, 32), 128>>>(gctx, Wo, bo, out);

    size_t total4 = ATT_ELEMS / 4;
    int blocks = (int)((total4 + 255) / 256);
    attn_norm<<<blocks, 256>>>(attnp);
}

// round 12
// speedup vs baseline: 2.5209x; 1.4098x over previous
#include <cuda_runtime.h>
#include <cuda_fp16.h>
#include <math.h>
#include <stdint.h>

#define BB 2
#define LQn 2048
#define LKn 2048
#define EE 1024
#define HH 16
#define DD 64

// ---------------- scratch (f16) ----------------
__device__ __half g_Q[(size_t)BB * LQn * EE];
__device__ __half g_K[(size_t)BB * LKn * EE];
__device__ __half g_V[(size_t)BB * LKn * EE];
__device__ __half g_ctx[(size_t)BB * LQn * EE];
__device__ __half g_P[(size_t)BB * HH * LQn * LKn];
__device__ __half g_Wh[(size_t)4 * EE * EE];          // Wq|Wk|Wv|Wo as f16
__device__ __half g_X[(size_t)3 * BB * LQn * EE];     // q_in|k_in|v_in as f16
__device__ float g_stats[(size_t)BB * HH * LQn];
__device__ float g_Sraw[(size_t)BB * HH * LQn * LKn];

// ---------------- helpers ----------------
__device__ __forceinline__ uint32_t h2(float x, float y) {
    __half2 h = __floats2half2_rn(x, y);
    return *(uint32_t*)&h;
}
__device__ __forceinline__ void mma16(float* d, uint32_t a0, uint32_t a1,
                                      uint32_t a2, uint32_t a3,
                                      uint32_t b0, uint32_t b1) {
    asm volatile(
        "mma.sync.aligned.m16n8k16.row.col.f32.f16.f16.f32 "
        "{%0,%1,%2,%3},{%4,%5,%6,%7},{%8,%9},{%0,%1,%2,%3};"
        : "+f"(d[0]), "+f"(d[1]), "+f"(d[2]), "+f"(d[3])
        : "r"(a0), "r"(a1), "r"(a2), "r"(a3), "r"(b0), "r"(b1));
}
__device__ __forceinline__ uint32_t smem_u32p(const void* p) {
    uint32_t a;
    asm("{ .reg .u64 t; cvta.to.shared.u64 t, %1; cvt.u32.u64 %0, t; }"
        : "=r"(a) : "l"(p));
    return a;
}
#define LDM4(d0, d1, d2, d3, a)                                            \
    asm volatile("ldmatrix.sync.aligned.m8n8.x4.shared.b16 {%0,%1,%2,%3}, [%4];" \
                 : "=r"(d0), "=r"(d1), "=r"(d2), "=r"(d3) : "r"(a))
#define LDM4T(d0, d1, d2, d3, a)                                           \
    asm volatile("ldmatrix.sync.aligned.m8n8.x4.trans.shared.b16 {%0,%1,%2,%3}, [%4];" \
                 : "=r"(d0), "=r"(d1), "=r"(d2), "=r"(d3) : "r"(a))
#define CP16(dst, src)                                                     \
    asm volatile("cp.async.cg.shared.global [%0], [%1], 16;"               \
                 :: "r"(dst), "l"(src))
#define CP_COMMIT() asm volatile("cp.async.commit_group;" ::: "memory")
#define CP_WAIT0()  asm volatile("cp.async.wait_group 0;" ::: "memory")

// ---------------- f32 -> f16 converters ----------------
__global__ __launch_bounds__(256) void conv_w(
    const float* __restrict__ w0, const float* __restrict__ w1,
    const float* __restrict__ w2, const float* __restrict__ w3)
{
    const float* src = (blockIdx.y == 0) ? w0 : (blockIdx.y == 1) ? w1
                     : (blockIdx.y == 2) ? w2 : w3;
    __half* dst = g_Wh + (size_t)blockIdx.y * EE * EE;
    size_t i = ((size_t)blockIdx.x * 256 + threadIdx.x) * 4;
    float4 v = *(const float4*)(src + i);
    *(uint2*)(dst + i) = make_uint2(h2(v.x, v.y), h2(v.z, v.w));
}
__global__ __launch_bounds__(256) void conv_x(
    const float* __restrict__ x0, const float* __restrict__ x1,
    const float* __restrict__ x2)
{
    const float* src = (blockIdx.y == 0) ? x0 : (blockIdx.y == 1) ? x1 : x2;
    __half* dst = g_X + (size_t)blockIdx.y * BB * LQn * EE;
    size_t i = ((size_t)blockIdx.x * 256 + threadIdx.x) * 4;
    float4 v = *(const float4*)(src + i);
    *(uint2*)(dst + i) = make_uint2(h2(v.x, v.y), h2(v.z, v.w));
}

// ============ f16 GEMM core: C[M,1024] = A @ W^T + bias ============
// 128x128 CTA, 128 threads (4 warps of 64x64), cp.async double-buffer, ldmatrix.
#define GST 40
#define GTILE_B (128 * GST * 2)

template <bool OUT_F32>
__device__ __forceinline__ void gemm_body(
    const __half* __restrict__ A, const __half* __restrict__ W,
    const float* __restrict__ bias, void* __restrict__ Cv,
    int m0, int n0)
{
    __shared__ __align__(16) __half Asm[2][128 * GST];
    __shared__ __align__(16) __half Wsm[2][128 * GST];

    const uint32_t as_b[2] = {smem_u32p(Asm[0]), smem_u32p(Asm[1])};
    const uint32_t ws_b[2] = {smem_u32p(Wsm[0]), smem_u32p(Wsm[1])};

    const int tid = threadIdx.x;
    const int lane = tid & 31;
    const int w = tid >> 5;
    const int wm = w >> 1, wn = w & 1;
    const int qr = lane >> 2;
    const int qc = 2 * (lane & 3);
    const int l7 = lane & 7;
    const int bit3 = ((lane >> 3) & 1) * 8;
    const int bit4 = ((lane >> 4) & 1) * 8;

    const __half* Ap = A + (size_t)(m0 + tid) * EE;
    const __half* Wp = W + (size_t)(n0 + tid) * EE;
    const uint32_t cpoff = (uint32_t)(tid * GST * 2);  // byte offset of row

    // prefetch chunk 0
#pragma unroll
    for (int i = 0; i < 4; i++) {
        CP16(as_b[0] + cpoff + i * 16, (const char*)Ap + i * 16);
        CP16(ws_b[0] + cpoff + i * 16, (const char*)Wp + i * 16);
    }
    CP_COMMIT();

    float acc[4][8][4];
#pragma unroll
    for (int mi = 0; mi < 4; mi++)
#pragma unroll
        for (int ni = 0; ni < 8; ni++)
#pragma unroll
            for (int e = 0; e < 4; e++) acc[mi][ni][e] = 0.0f;

    for (int kc = 0; kc < 32; kc++) {
        const int buf = kc & 1;
        CP_WAIT0();
        __syncthreads();
        if (kc < 31) {
            const char* an = (const char*)(Ap + (kc + 1) * 32);
            const char* wn2 = (const char*)(Wp + (kc + 1) * 32);
#pragma unroll
            for (int i = 0; i < 4; i++) {
                CP16(as_b[buf ^ 1] + cpoff + i * 16, an + i * 16);
                CP16(ws_b[buf ^ 1] + cpoff + i * 16, wn2 + i * 16);
            }
            CP_COMMIT();
        }
#pragma unroll
        for (int ks = 0; ks < 2; ks++) {
            uint32_t af[4][4];
#pragma unroll
            for (int mi = 0; mi < 4; mi++) {
                uint32_t a = as_b[buf] +
                    ((wm * 64 + mi * 16 + bit3 + l7) * GST + ks * 16 + bit4) * 2;
                LDM4(af[mi][0], af[mi][1], af[mi][2], af[mi][3], a);
            }
#pragma unroll
            for (int nii = 0; nii < 4; nii++) {
                uint32_t b0, b1, b2, b3;
                uint32_t a = ws_b[buf] +
                    ((wn * 64 + nii * 16 + bit4 + l7) * GST + ks * 16 + bit3) * 2;
                LDM4(b0, b1, b2, b3, a);
#pragma unroll
                for (int mi = 0; mi < 4; mi++) {
                    mma16(acc[mi][2 * nii],     af[mi][0], af[mi][1], af[mi][2], af[mi][3], b0, b1);
                    mma16(acc[mi][2 * nii + 1], af[mi][0], af[mi][1], af[mi][2], af[mi][3], b2, b3);
                }
            }
        }
        __syncthreads();
    }

#pragma unroll
    for (int mi = 0; mi < 4; mi++) {
        int rl = m0 + wm * 64 + mi * 16 + qr;
#pragma unroll
        for (int ni = 0; ni < 8; ni++) {
            int cc = n0 + wn * 64 + ni * 8 + qc;
            float2 bv = *(const float2*)&bias[cc];
            if (OUT_F32) {
                float* C = (float*)Cv;
                *(float2*)&C[(size_t)rl * EE + cc] =
                    make_float2(acc[mi][ni][0] + bv.x, acc[mi][ni][1] + bv.y);
                *(float2*)&C[(size_t)(rl + 8) * EE + cc] =
                    make_float2(acc[mi][ni][2] + bv.x, acc[mi][ni][3] + bv.y);
            } else {
                __half* C = (__half*)Cv;
                *(uint32_t*)&C[(size_t)rl * EE + cc] =
                    h2(acc[mi][ni][0] + bv.x, acc[mi][ni][1] + bv.y);
                *(uint32_t*)&C[(size_t)(rl + 8) * EE + cc] =
                    h2(acc[mi][ni][2] + bv.x, acc[mi][ni][3] + bv.y);
            }
        }
    }
}

__global__ __launch_bounds__(128, 2) void gemm_qkv(
    const float* __restrict__ b0p, const float* __restrict__ b1p,
    const float* __restrict__ b2p)
{
    const int z = blockIdx.z;
    const __half* A = g_X + (size_t)z * BB * LQn * EE;
    const __half* W = g_Wh + (size_t)z * EE * EE;
    const float* bias = (z == 0) ? b0p : (z == 1) ? b1p : b2p;
    __half* C = (z == 0) ? g_Q : (z == 1) ? g_K : g_V;
    gemm_body<false>(A, W, bias, C, blockIdx.y * 128, blockIdx.x * 128);
}

__global__ __launch_bounds__(128, 2) void gemm_out(
    const float* __restrict__ bias, float* __restrict__ C)
{
    gemm_body<true>(g_ctx, g_Wh + (size_t)3 * EE * EE, bias, C,
                    blockIdx.y * 128, blockIdx.x * 128);
}

// ============ Attention (f16 mma + ldmatrix + cp.async, f16 p-store) ============
#define QP 72
#define TILE_B (128 * QP * 2)
#define ATT_DYN (5 * TILE_B + 1024)

__global__ __launch_bounds__(256, 1) void attn_tc(const int* __restrict__ mask)
{
    extern __shared__ char smc[];
    float* lred = (float*)(smc + 5 * TILE_B);
    float* Osm = (float*)smc;

    const uint32_t sb = smem_u32p(smc);
    const uint32_t qs_b = sb;
    const uint32_t ks_b[2] = {sb + TILE_B, sb + 2 * TILE_B};
    const uint32_t vs_b[2] = {sb + 3 * TILE_B, sb + 4 * TILE_B};

    const int tid = threadIdx.x;
    const int lane = tid & 31;
    const int w = tid >> 5;
    const int qr = lane >> 2;
    const int qc = 2 * (lane & 3);
    const int wq = w >> 1;
    const int wk = w & 1;
    const int qb = wq * 32;
    const int l7 = lane & 7;
    const int bit3 = ((lane >> 3) & 1) * 8;
    const int bit4 = ((lane >> 4) & 1) * 8;

    const int q0 = blockIdx.x * 128;
    const int h = blockIdx.y;
    const int b = blockIdx.z;

    const int cr = tid >> 1;
    const int cc32 = (tid & 1) * 32;
    const uint32_t cpdst = (uint32_t)((cr * QP + cc32) * 2);

    const __half* Kg0 = g_K + (size_t)(b * LKn + cr) * EE + h * DD + cc32;
    const __half* Vg0 = g_V + (size_t)(b * LKn + cr) * EE + h * DD + cc32;

    {
#pragma unroll
        for (int i = 0; i < 4; i++) {
            CP16(ks_b[0] + cpdst + i * 16, (const char*)Kg0 + i * 16);
            CP16(vs_b[0] + cpdst + i * 16, (const char*)Vg0 + i * 16);
        }
        CP_COMMIT();
    }
    {
        __half* Qs = (__half*)smc;
        const __half* Qg = g_Q + (size_t)(b * LQn + q0 + cr) * EE + h * DD + cc32;
        uint4* dst = (uint4*)&Qs[cr * QP + cc32];
        const uint4* src = (const uint4*)Qg;
#pragma unroll
        for (int i = 0; i < 4; i++) dst[i] = src[i];
    }

    float oacc[2][8][4];
#pragma unroll
    for (int mi = 0; mi < 2; mi++)
#pragma unroll
        for (int ni = 0; ni < 8; ni++)
#pragma unroll
            for (int e = 0; e < 4; e++) oacc[mi][ni][e] = 0.0f;

    float lacc[2][2] = {{0.0f, 0.0f}, {0.0f, 0.0f}};

    const int* mptr[2][2];
    __half* pptr[2][2];
#pragma unroll
    for (int mi = 0; mi < 2; mi++)
#pragma unroll
        for (int hi = 0; hi < 2; hi++) {
            int q = q0 + qb + mi * 16 + hi * 8 + qr;
            mptr[mi][hi] = mask + ((size_t)b * LQn + q) * LKn + wk * 64;
            pptr[mi][hi] = g_P + ((size_t)(b * HH + h) * LQn + q) * LKn + wk * 64;
        }

    for (int c = 0; c < 16; c++) {
        const int buf = c & 1;
        CP_WAIT0();
        __syncthreads();
        if (c < 15) {
            const char* ks = (const char*)(Kg0 + (size_t)(c + 1) * 128 * EE);
            const char* vs = (const char*)(Vg0 + (size_t)(c + 1) * 128 * EE);
#pragma unroll
            for (int i = 0; i < 4; i++) {
                CP16(ks_b[buf ^ 1] + cpdst + i * 16, ks + i * 16);
                CP16(vs_b[buf ^ 1] + cpdst + i * 16, vs + i * 16);
            }
            CP_COMMIT();
        }

        float sacc[2][8][4];
#pragma unroll
        for (int mi = 0; mi < 2; mi++)
#pragma unroll
            for (int ni = 0; ni < 8; ni++)
#pragma unroll
                for (int e = 0; e < 4; e++) sacc[mi][ni][e] = 0.0f;

#pragma unroll
        for (int ks = 0; ks < 4; ks++) {
            uint32_t af[2][4];
#pragma unroll
            for (int mi = 0; mi < 2; mi++) {
                uint32_t a = qs_b + ((qb + mi * 16 + bit3 + l7) * QP + ks * 16 + bit4) * 2;
                LDM4(af[mi][0], af[mi][1], af[mi][2], af[mi][3], a);
            }
#pragma unroll
            for (int nii = 0; nii < 4; nii++) {
                uint32_t b0, b1, b2, b3;
                uint32_t a = ks_b[buf] + ((wk * 64 + nii * 16 + bit4 + l7) * QP + ks * 16 + bit3) * 2;
                LDM4(b0, b1, b2, b3, a);
                mma16(sacc[0][2 * nii],     af[0][0], af[0][1], af[0][2], af[0][3], b0, b1);
                mma16(sacc[1][2 * nii],     af[1][0], af[1][1], af[1][2], af[1][3], b0, b1);
                mma16(sacc[0][2 * nii + 1], af[0][0], af[0][1], af[0][2], af[0][3], b2, b3);
                mma16(sacc[1][2 * nii + 1], af[1][0], af[1][1], af[1][2], af[1][3], b2, b3);
            }
        }

#pragma unroll
        for (int mi = 0; mi < 2; mi++) {
#pragma unroll
            for (int ni = 0; ni < 8; ni++) {
                int cb = ni * 8 + qc;
                int2 m2lo = *(const int2*)(mptr[mi][0] + c * 128 + cb);
                int2 m2hi = *(const int2*)(mptr[mi][1] + c * 128 + cb);
                float s0 = sacc[mi][ni][0] * 0.125f; if (m2lo.x == 0) s0 = -1.0e30f;
                float s1 = sacc[mi][ni][1] * 0.125f; if (m2lo.y == 0) s1 = -1.0e30f;
                float s2 = sacc[mi][ni][2] * 0.125f; if (m2hi.x == 0) s2 = -1.0e30f;
                float s3 = sacc[mi][ni][3] * 0.125f; if (m2hi.y == 0) s3 = -1.0e30f;
                float p0 = __expf(s0), p1 = __expf(s1);
                float p2 = __expf(s2), p3 = __expf(s3);
                *(uint32_t*)(pptr[mi][0] + c * 128 + cb) = h2(p0, p1);
                *(uint32_t*)(pptr[mi][1] + c * 128 + cb) = h2(p2, p3);
                lacc[mi][0] += p0 + p1;
                lacc[mi][1] += p2 + p3;
                sacc[mi][ni][0] = p0; sacc[mi][ni][1] = p1;
                sacc[mi][ni][2] = p2; sacc[mi][ni][3] = p3;
            }
        }

#pragma unroll
        for (int j = 0; j < 4; j++) {
            uint32_t a0[2], a1[2], a2[2], a3[2];
#pragma unroll
            for (int mi = 0; mi < 2; mi++) {
                a0[mi] = h2(sacc[mi][2 * j][0], sacc[mi][2 * j][1]);
                a1[mi] = h2(sacc[mi][2 * j][2], sacc[mi][2 * j][3]);
                a2[mi] = h2(sacc[mi][2 * j + 1][0], sacc[mi][2 * j + 1][1]);
                a3[mi] = h2(sacc[mi][2 * j + 1][2], sacc[mi][2 * j + 1][3]);
            }
#pragma unroll
            for (int nii = 0; nii < 4; nii++) {
                uint32_t b0, b1, b2, b3;
                uint32_t a = vs_b[buf] + ((wk * 64 + j * 16 + bit3 + l7) * QP + nii * 16 + bit4) * 2;
                LDM4T(b0, b1, b2, b3, a);
                mma16(oacc[0][2 * nii],     a0[0], a1[0], a2[0], a3[0], b0, b1);
                mma16(oacc[1][2 * nii],     a0[1], a1[1], a2[1], a3[1], b0, b1);
                mma16(oacc[0][2 * nii + 1], a0[0], a1[0], a2[0], a3[0], b2, b3);
                mma16(oacc[1][2 * nii + 1], a0[1], a1[1], a2[1], a3[1], b2, b3);
            }
        }
    }

#pragma unroll
    for (int mi = 0; mi < 2; mi++)
#pragma unroll
        for (int hi = 0; hi < 2; hi++) {
            float v = lacc[mi][hi];
            v += __shfl_xor_sync(0xFFFFFFFF, v, 1);
            v += __shfl_xor_sync(0xFFFFFFFF, v, 2);
            if ((lane & 3) == 0)
                lred[wk * 128 + qb + mi * 16 + hi * 8 + qr] = v;
        }
    __syncthreads();

    if (wk == 1) {
#pragma unroll
        for (int mi = 0; mi < 2; mi++) {
            int row = qb + mi * 16 + qr;
#pragma unroll
            for (int ni = 0; ni < 8; ni++) {
                *(float2*)&Osm[row * 68 + ni * 8 + qc] =
                    make_float2(oacc[mi][ni][0], oacc[mi][ni][1]);
                *(float2*)&Osm[(row + 8) * 68 + ni * 8 + qc] =
                    make_float2(oacc[mi][ni][2], oacc[mi][ni][3]);
            }
        }
    }
    __syncthreads();

    if (wk == 0) {
#pragma unroll
        for (int mi = 0; mi < 2; mi++) {
#pragma unroll
            for (int hi = 0; hi < 2; hi++) {
                int rrow = qb + mi * 16 + hi * 8 + qr;
                float l = lred[rrow] + lred[128 + rrow];
                float inv = 1.0f / l;
                __half* og = g_ctx + (size_t)(b * LQn + q0 + rrow) * EE + h * DD;
#pragma unroll
                for (int ni = 0; ni < 8; ni++) {
                    float2 part = *(const float2*)&Osm[rrow * 68 + ni * 8 + qc];
                    *(uint32_t*)&og[ni * 8 + qc] = h2(
                        (oacc[mi][ni][hi * 2 + 0] + part.x) * inv,
                        (oacc[mi][ni][hi * 2 + 1] + part.y) * inv);
                }
                if ((lane & 3) == 0)
                    g_stats[(size_t)(b * HH + h) * LQn + q0 + rrow] = l;
            }
        }
    }
}

// ---------------- normalize: attn = h2f(p_f16) / l (8 outputs/thread) ----------------
__global__ __launch_bounds__(256) void attn_norm(float* __restrict__ attn)
{
    size_t i8 = (size_t)blockIdx.x * blockDim.x + threadIdx.x;
    size_t row = (i8 * 8) >> 11;
    float invl = 1.0f / g_stats[row];
    uint4 pv = *(const uint4*)(g_P + i8 * 8);
    float2 f0 = __half22float2(*(__half2*)&pv.x);
    float2 f1 = __half22float2(*(__half2*)&pv.y);
    float2 f2 = __half22float2(*(__half2*)&pv.z);
    float2 f3 = __half22float2(*(__half2*)&pv.w);
    float4* op = (float4*)(attn + i8 * 8);
    op[0] = make_float4(f0.x * invl, f0.y * invl, f1.x * invl, f1.y * invl);
    op[1] = make_float4(f2.x * invl, f2.y * invl, f3.x * invl, f3.y * invl);
}

// ---------------- launch ----------------
extern "C" void kernel_launch(void* const* d_in, const int* in_sizes, int n_in,
                              void* d_out, int out_size)
{
    const float* q_in = (const float*)d_in[0];
    const float* k_in = (const float*)d_in[1];
    const float* v_in = (const float*)d_in[2];
    const int*   mask = (const int*)d_in[3];
    const float* Wq = (const float*)d_in[4];
    const float* bq = (const float*)d_in[5];
    const float* Wk = (const float*)d_in[6];
    const float* bk = (const float*)d_in[7];
    const float* Wv = (const float*)d_in[8];
    const float* bv = (const float*)d_in[9];
    const float* Wo = (const float*)d_in[10];
    const float* bo = (const float*)d_in[11];

    float* out = (float*)d_out;

    float* gSraw;
    cudaGetSymbolAddress((void**)&gSraw, g_Sraw);

    const size_t OUT_ELEMS = (size_t)BB * LQn * EE;
    const size_t ATT_ELEMS = (size_t)BB * HH * LQn * LKn;
    bool attn_is_output = ((size_t)out_size >= OUT_ELEMS + ATT_ELEMS);
    float* attnp = attn_is_output ? (out + OUT_ELEMS) : gSraw;

    cudaFuncSetAttribute(attn_tc, cudaFuncAttributeMaxDynamicSharedMemorySize, ATT_DYN);

    // convert weights + inputs to f16 scratch
    conv_w<<<dim3(EE * EE / 1024, 4), 256>>>(Wq, Wk, Wv, Wo);
    conv_x<<<dim3(BB * LQn * EE / 1024, 3), 256>>>(q_in, k_in, v_in);

    dim3 qkvGrid(8, 32, 3);
    gemm_qkv<<<qkvGrid, 128>>>(bq, bk, bv);

    dim3 attnGrid(LQn / 128, HH, BB);
    attn_tc<<<attnGrid, 256, ATT_DYN>>>(mask);

    gemm_out<<<dim3(8, 32), 128>>>(bo, out);

    size_t total8 = ATT_ELEMS / 8;
    int blocks = (int)((total8 + 255) / 256);
    attn_norm<<<blocks, 256>>>(attnp);
}